// round 1
// baseline (speedup 1.0000x reference)
#include <cuda_runtime.h>

// Problem constants
#define TT 2048
#define NN 64
#define EE 1024
#define DD 1024
#define AA 512
#define TCH 16   // t-chunks for ctx partial

// Scratch (no allocation allowed -> device globals)
__device__ float g_dproj[NN * AA];
__device__ float g_scoresT[NN * TT];
__device__ float g_alphaT[NN * TT];
__device__ float g_part[TCH * NN * EE];

typedef unsigned long long u64;

__device__ __forceinline__ u64 pack_dup(float x) {
    u64 r; asm("mov.b64 %0, {%1, %1};" : "=l"(r) : "f"(x)); return r;
}
__device__ __forceinline__ void ffma2(u64& acc, u64 a, u64 b) {
    asm("fma.rn.f32x2 %0, %1, %2, %0;" : "+l"(acc) : "l"(a), "l"(b));
}
__device__ __forceinline__ float2 unpack2(u64 p) {
    float2 r; asm("mov.b64 {%0, %1}, %2;" : "=f"(r.x), "=f"(r.y) : "l"(p)); return r;
}

// ---------------------------------------------------------------------------
// Kernel 1: d_proj[n][a] = sum_d dec_h[n][d] * W_d[a][d]   (warp per output)
// ---------------------------------------------------------------------------
__global__ void dproj_kernel(const float* __restrict__ dec_h,
                             const float* __restrict__ W_d) {
    int w = (blockIdx.x * blockDim.x + threadIdx.x) >> 5;
    int lane = threadIdx.x & 31;
    if (w >= NN * AA) return;
    int n = w / AA, a = w % AA;
    const float4* dh = (const float4*)(dec_h + (size_t)n * DD);
    const float4* wd = (const float4*)(W_d + (size_t)a * DD);
    float s = 0.f;
    #pragma unroll
    for (int i = lane; i < DD / 4; i += 32) {
        float4 x = dh[i], y = wd[i];
        s += x.x * y.x + x.y * y.y + x.z * y.z + x.w * y.w;
    }
    #pragma unroll
    for (int o = 16; o; o >>= 1) s += __shfl_down_sync(0xffffffffu, s, o);
    if (lane == 0) g_dproj[n * AA + a] = s;
}

// ---------------------------------------------------------------------------
// Kernel 2: fused scores. One block per t (rows = n 0..63).
//   scores[t][n] = sum_a tanh( enc[t,n,:]·W_e[a,:] + dproj[n][a] ) * v[a]
// Tiled GEMM BM=64 (all n), BN=128 (a chunk), BK=16, fp32 via packed f32x2 FMA.
// ---------------------------------------------------------------------------
#define BK 16
#define BM 64
#define BN 128

__global__ __launch_bounds__(256) void scores_kernel(
    const float* __restrict__ enc, const float* __restrict__ We,
    const float* __restrict__ v) {
    __shared__ __align__(16) float Xs[BK][BM];
    __shared__ __align__(16) float Ws[BK][BN];
    __shared__ float red[BM][17];

    const int t = blockIdx.x;
    const int tid = threadIdx.x;
    const int r0 = (tid >> 4) * 4;   // 4 rows (n)
    const int c0 = (tid & 15) * 8;   // 8 cols (a)

    // gmem->smem load mapping
    const int xr = tid >> 2;          // row 0..63
    const int xk = (tid & 3) * 4;     // k 0,4,8,12
    const int wa = tid >> 1;          // a_local 0..127
    const int wk = (tid & 1) * 8;     // k 0 or 8

    const float* Xbase = enc + (size_t)t * (NN * EE);

    float sc[4] = {0.f, 0.f, 0.f, 0.f};

    for (int aT = 0; aT < AA / BN; ++aT) {
        const int a0 = aT * BN;
        u64 acc[4][4];
        #pragma unroll
        for (int i = 0; i < 4; ++i)
            #pragma unroll
            for (int j = 0; j < 4; ++j) acc[i][j] = 0ull;

        for (int kt = 0; kt < EE / BK; ++kt) {
            const int k0 = kt * BK;
            float4 xv  = *(const float4*)(Xbase + (size_t)xr * EE + k0 + xk);
            float4 wv0 = *(const float4*)(We + (size_t)(a0 + wa) * EE + k0 + wk);
            float4 wv1 = *(const float4*)(We + (size_t)(a0 + wa) * EE + k0 + wk + 4);

            __syncthreads();
            Xs[xk + 0][xr] = xv.x;  Xs[xk + 1][xr] = xv.y;
            Xs[xk + 2][xr] = xv.z;  Xs[xk + 3][xr] = xv.w;
            Ws[wk + 0][wa] = wv0.x; Ws[wk + 1][wa] = wv0.y;
            Ws[wk + 2][wa] = wv0.z; Ws[wk + 3][wa] = wv0.w;
            Ws[wk + 4][wa] = wv1.x; Ws[wk + 5][wa] = wv1.y;
            Ws[wk + 6][wa] = wv1.z; Ws[wk + 7][wa] = wv1.w;
            __syncthreads();

            #pragma unroll
            for (int k = 0; k < BK; ++k) {
                float4 x = *(const float4*)&Xs[k][r0];
                u64 xd0 = pack_dup(x.x), xd1 = pack_dup(x.y);
                u64 xd2 = pack_dup(x.z), xd3 = pack_dup(x.w);
                ulonglong2 wA = *(const ulonglong2*)&Ws[k][c0];
                ulonglong2 wB = *(const ulonglong2*)&Ws[k][c0 + 4];
                ffma2(acc[0][0], xd0, wA.x); ffma2(acc[0][1], xd0, wA.y);
                ffma2(acc[0][2], xd0, wB.x); ffma2(acc[0][3], xd0, wB.y);
                ffma2(acc[1][0], xd1, wA.x); ffma2(acc[1][1], xd1, wA.y);
                ffma2(acc[1][2], xd1, wB.x); ffma2(acc[1][3], xd1, wB.y);
                ffma2(acc[2][0], xd2, wA.x); ffma2(acc[2][1], xd2, wA.y);
                ffma2(acc[2][2], xd2, wB.x); ffma2(acc[2][3], xd2, wB.y);
                ffma2(acc[3][0], xd3, wA.x); ffma2(acc[3][1], xd3, wA.y);
                ffma2(acc[3][2], xd3, wB.x); ffma2(acc[3][3], xd3, wB.y);
            }
        }

        // epilogue: + dproj, tanh, dot with v
        #pragma unroll
        for (int i = 0; i < 4; ++i) {
            const int n = r0 + i;
            #pragma unroll
            for (int j = 0; j < 4; ++j) {
                float2 p = unpack2(acc[i][j]);
                const int a = a0 + c0 + 2 * j;
                p.x += g_dproj[n * AA + a];
                p.y += g_dproj[n * AA + a + 1];
                sc[i] += tanhf(p.x) * __ldg(&v[a]) + tanhf(p.y) * __ldg(&v[a + 1]);
            }
        }
    }

    // cross-thread reduce over the 16 column-threads of each row
    #pragma unroll
    for (int i = 0; i < 4; ++i) red[r0 + i][tid & 15] = sc[i];
    __syncthreads();
    if (tid < BM) {
        float s = 0.f;
        #pragma unroll
        for (int j = 0; j < 16; ++j) s += red[tid][j];
        g_scoresT[tid * TT + blockIdx.x] = s;
    }
}

// ---------------------------------------------------------------------------
// Kernel 3: softmax over T per column n. Writes alpha (d_out) and alphaT.
// ---------------------------------------------------------------------------
__global__ void softmax_kernel(float* __restrict__ out_alpha) {
    const int n = blockIdx.x, tid = threadIdx.x;
    __shared__ float sm[256];
    const float* s = g_scoresT + (size_t)n * TT;

    float m = -1e30f;
    for (int t = tid; t < TT; t += 256) m = fmaxf(m, s[t]);
    sm[tid] = m; __syncthreads();
    #pragma unroll
    for (int o = 128; o; o >>= 1) {
        if (tid < o) sm[tid] = fmaxf(sm[tid], sm[tid + o]);
        __syncthreads();
    }
    m = sm[0];
    __syncthreads();

    float acc = 0.f;
    for (int t = tid; t < TT; t += 256) acc += expf(s[t] - m);
    sm[tid] = acc; __syncthreads();
    #pragma unroll
    for (int o = 128; o; o >>= 1) {
        if (tid < o) sm[tid] += sm[tid + o];
        __syncthreads();
    }
    const float inv = 1.0f / sm[0];

    for (int t = tid; t < TT; t += 256) {
        float al = expf(s[t] - m) * inv;
        g_alphaT[(size_t)n * TT + t] = al;
        out_alpha[(size_t)t * NN + n] = al;
    }
}

// ---------------------------------------------------------------------------
// Kernel 4: ctx partials. Block = (n, t-chunk). ctx_p = sum_t alpha*enc.
// ---------------------------------------------------------------------------
__global__ __launch_bounds__(256) void ctx_partial_kernel(const float* __restrict__ enc) {
    const int tc = blockIdx.x & (TCH - 1);
    const int n = blockIdx.x / TCH;
    const int e0 = threadIdx.x * 4;
    float4 acc = make_float4(0.f, 0.f, 0.f, 0.f);
    const int tBeg = tc * (TT / TCH);
    #pragma unroll 4
    for (int t = tBeg; t < tBeg + TT / TCH; ++t) {
        float al = g_alphaT[(size_t)n * TT + t];
        float4 ev = *(const float4*)(enc + ((size_t)t * NN + n) * EE + e0);
        acc.x += al * ev.x; acc.y += al * ev.y;
        acc.z += al * ev.z; acc.w += al * ev.w;
    }
    *(float4*)&g_part[((size_t)tc * NN + n) * EE + e0] = acc;
}

// ---------------------------------------------------------------------------
// Kernel 5: reduce ctx partials into d_out.
// ---------------------------------------------------------------------------
__global__ void ctx_reduce_kernel(float* __restrict__ out_ctx) {
    const int n = blockIdx.x;
    const int e0 = threadIdx.x * 4;
    float4 acc = make_float4(0.f, 0.f, 0.f, 0.f);
    #pragma unroll
    for (int tc = 0; tc < TCH; ++tc) {
        float4 p = *(const float4*)&g_part[((size_t)tc * NN + n) * EE + e0];
        acc.x += p.x; acc.y += p.y; acc.z += p.z; acc.w += p.w;
    }
    *(float4*)&out_ctx[(size_t)n * EE + e0] = acc;
}

// ---------------------------------------------------------------------------
extern "C" void kernel_launch(void* const* d_in, const int* in_sizes, int n_in,
                              void* d_out, int out_size) {
    const float* enc = (const float*)d_in[0];   // [T, N, E]
    const float* dec = (const float*)d_in[1];   // [N, D]
    const float* We  = (const float*)d_in[2];   // [A, E]
    const float* Wd  = (const float*)d_in[3];   // [A, D]
    const float* v   = (const float*)d_in[4];   // [1, A]

    float* out = (float*)d_out;
    float* out_ctx = out;                 // [N, E]
    float* out_alpha = out + NN * EE;     // [T, N]

    dproj_kernel<<<(NN * AA) / 8, 256>>>(dec, Wd);
    scores_kernel<<<TT, 256>>>(enc, We, v);
    softmax_kernel<<<NN, 256>>>(out_alpha);
    ctx_partial_kernel<<<NN * TCH, 256>>>(enc);
    ctx_reduce_kernel<<<NN, 256>>>(out_ctx);
}

// round 3
// speedup vs baseline: 3.0356x; 3.0356x over previous
#include <cuda_runtime.h>
#include <cuda_bf16.h>
#include <cstdint>

#define TT 2048
#define NN 64
#define EE 1024
#define DD 1024
#define AA 512
#define TCH 16

#define KSX 64      // k-steps from enc (1024/16)
#define KST 68      // + 4 one-hot k-steps carrying dproj

// ---------------- device scratch ----------------
__device__ float g_scoresT[NN * TT];
__device__ float g_alphaT[NN * TT];
__device__ float g_part[TCH * NN * EE];
__device__ __align__(16) __nv_bfloat16 g_Whi[KST * AA * 16];  // [s][a][k16]
__device__ __align__(16) __nv_bfloat16 g_Wlo[KST * AA * 16];

// ---------------- helpers ----------------
__device__ __forceinline__ uint32_t smem_u32(const void* p) {
    uint32_t a;
    asm("{ .reg .u64 t; cvta.to.shared.u64 t, %1; cvt.u32.u64 %0, t; }" : "=r"(a) : "l"(p));
    return a;
}
__device__ __forceinline__ void ldmx4(uint32_t* r, uint32_t a) {
    asm volatile("ldmatrix.sync.aligned.m8n8.x4.shared.b16 {%0,%1,%2,%3}, [%4];"
                 : "=r"(r[0]), "=r"(r[1]), "=r"(r[2]), "=r"(r[3]) : "r"(a));
}
__device__ __forceinline__ void ldmx2(uint32_t& r0, uint32_t& r1, uint32_t a) {
    asm volatile("ldmatrix.sync.aligned.m8n8.x2.shared.b16 {%0,%1}, [%2];"
                 : "=r"(r0), "=r"(r1) : "r"(a));
}
__device__ __forceinline__ void mma16816(float* d, const uint32_t* a, uint32_t b0, uint32_t b1) {
    asm volatile(
        "mma.sync.aligned.m16n8k16.row.col.f32.bf16.bf16.f32 "
        "{%0,%1,%2,%3}, {%4,%5,%6,%7}, {%8,%9}, {%0,%1,%2,%3};"
        : "+f"(d[0]), "+f"(d[1]), "+f"(d[2]), "+f"(d[3])
        : "r"(a[0]), "r"(a[1]), "r"(a[2]), "r"(a[3]), "r"(b0), "r"(b1));
}
__device__ __forceinline__ void cp16(uint32_t dst, const void* src) {
    asm volatile("cp.async.cg.shared.global [%0], [%1], 16;" :: "r"(dst), "l"(src) : "memory");
}
__device__ __forceinline__ void cp_commit() { asm volatile("cp.async.commit_group;" ::: "memory"); }
__device__ __forceinline__ void cp_wait1()  { asm volatile("cp.async.wait_group 1;" ::: "memory"); }
__device__ __forceinline__ void cp_wait0()  { asm volatile("cp.async.wait_group 0;" ::: "memory"); }
__device__ __forceinline__ float tanh_fast(float x) {
    float e = __expf(2.0f * x);
    return 1.0f - __fdividef(2.0f, e + 1.0f);
}

// ---------------- smem layout (bytes) ----------------
#define A_OFF(buf, p) ((uint32_t)((buf) * 4096 + (p) * 2048))            // 64 rows x 32B
#define W_OFF(buf, p) ((uint32_t)(8192 + (buf) * 32768 + (p) * 16384))   // 512 rows x 32B
#define RED_OFF 73728u
#define SMEMSZ  75776

// ---------------------------------------------------------------------------
// prep: split W_e into bf16 hi/lo, k-chunked layout [s][a][k16]
// ---------------------------------------------------------------------------
__global__ void prepW_kernel(const float* __restrict__ We) {
    int i = blockIdx.x * blockDim.x + threadIdx.x;
    if (i >= AA * EE) return;
    int a = i >> 10, e = i & 1023;
    float x = We[i];
    __nv_bfloat16 hb = __float2bfloat16(x);
    float lf = x - __bfloat162float(hb);
    int s = e >> 4, kk = e & 15;
    size_t o = ((size_t)s * AA + a) * 16 + kk;
    g_Whi[o] = hb;
    g_Wlo[o] = __float2bfloat16(lf);
}

// ---------------------------------------------------------------------------
// dproj[n][a] = dec_h[n]·W_d[a]; written as hi/lo into one-hot k-steps 64..67
// ---------------------------------------------------------------------------
__global__ void dproj_kernel(const float* __restrict__ dec_h,
                             const float* __restrict__ W_d) {
    int w = (blockIdx.x * blockDim.x + threadIdx.x) >> 5;
    int lane = threadIdx.x & 31;
    if (w >= NN * AA) return;
    int n = w / AA, a = w % AA;
    const float4* dh = (const float4*)(dec_h + (size_t)n * DD);
    const float4* wd = (const float4*)(W_d + (size_t)a * DD);
    float s = 0.f;
    #pragma unroll
    for (int i = lane; i < DD / 4; i += 32) {
        float4 x = dh[i], y = wd[i];
        s += x.x * y.x + x.y * y.y + x.z * y.z + x.w * y.w;
    }
    #pragma unroll
    for (int o = 16; o; o >>= 1) s += __shfl_down_sync(0xffffffffu, s, o);
    if (lane == 0) {
        __nv_bfloat16 hb = __float2bfloat16(s);
        float lf = s - __bfloat162float(hb);
        size_t slot = ((size_t)(KSX + (n >> 4)) * AA + a) * 16 + (n & 15);
        g_Whi[slot] = hb;
        g_Wlo[slot] = __float2bfloat16(lf);
    }
}

// ---------------------------------------------------------------------------
// scores: one block per t. rows = n (64), cols = a (512).
// D = [Xhi|onehot]·[Whi]ᵀ (+ hi·lo + lo·hi), then tanh·v reduce.
// ---------------------------------------------------------------------------
__global__ __launch_bounds__(256, 1) void scores_mma_kernel(
    const float* __restrict__ enc, const float* __restrict__ v) {
    extern __shared__ char smem[];
    const uint32_t sb = smem_u32(smem);
    const int tid = threadIdx.x;
    const int tile = blockIdx.x;
    const int lane = tid & 31;
    const int wid = tid >> 5;           // 0..7 -> n-range wid*64
    const int row = tid >> 2;           // X loader row 0..63
    const int k4 = (tid & 3) * 4;       // X loader k offset

    const size_t rowBase = ((size_t)tile * 64 + row) * EE;

    // accumulators: 4 m-frags x 8 n-tiles x 4
    float c[4][8][4] = {};

    // ---- loaders ----
    float4 xreg = make_float4(0.f, 0.f, 0.f, 0.f);
    if (0 < KSX) xreg = *(const float4*)(enc + rowBase + k4);

    const int n0 = tid * 2;  // W copy rows (2 per thread)
    auto cpW = [&](int s, int b) {
        const char* srcH = (const char*)(g_Whi + ((size_t)s * AA + n0) * 16);
        const char* srcL = (const char*)(g_Wlo + ((size_t)s * AA + n0) * 16);
        uint32_t dH = sb + W_OFF(b, 0) + n0 * 32;
        uint32_t dL = sb + W_OFF(b, 1) + n0 * 32;
        #pragma unroll
        for (int q = 0; q < 4; q++) {
            cp16(dH + q * 16, srcH + q * 16);
            cp16(dL + q * 16, srcL + q * 16);
        }
    };

    auto stsA = [&](int s, int b) {
        unsigned short h[4], l[4];
        if (s < KSX) {
            float f[4] = {xreg.x, xreg.y, xreg.z, xreg.w};
            #pragma unroll
            for (int j = 0; j < 4; j++) {
                __nv_bfloat16 hb = __float2bfloat16(f[j]);
                float lf = f[j] - __bfloat162float(hb);
                __nv_bfloat16 lb = __float2bfloat16(lf);
                h[j] = *(unsigned short*)&hb;
                l[j] = *(unsigned short*)&lb;
            }
        } else {
            #pragma unroll
            for (int j = 0; j < 4; j++) { h[j] = 0; l[j] = 0; }
            if ((row >> 4) == (s - KSX)) {
                int kk = (row & 15) - k4;
                if (kk >= 0 && kk < 4) h[kk] = 0x3F80;  // bf16 1.0
            }
        }
        uint2 hp, lp;
        hp.x = ((uint32_t)h[1] << 16) | h[0]; hp.y = ((uint32_t)h[3] << 16) | h[2];
        lp.x = ((uint32_t)l[1] << 16) | l[0]; lp.y = ((uint32_t)l[3] << 16) | l[2];
        *(uint2*)(smem + A_OFF(b, 0) + row * 32 + k4 * 2) = hp;
        *(uint2*)(smem + A_OFF(b, 1) + row * 32 + k4 * 2) = lp;
    };

    // ---- ldmatrix address components ----
    const uint32_t aRowOff = (uint32_t)(lane & 15) * 32 + (uint32_t)(lane >> 4) * 16;
    const uint32_t bRowOff = (uint32_t)(wid * 64 + (lane & 7)) * 32 +
                             (uint32_t)((lane >> 3) & 1) * 16;

    // ---- prologue ----
    cpW(0, 0); cp_commit();

    #pragma unroll 1
    for (int s = 0; s < KST; s++) {
        const int b = s & 1;
        stsA(s, b);
        if (s + 1 < KST) {
            if (s + 1 < KSX)
                xreg = *(const float4*)(enc + rowBase + (size_t)(s + 1) * 16 + k4);
            cpW(s + 1, b ^ 1);
            cp_commit();
            cp_wait1();
        } else {
            cp_wait0();
        }
        __syncthreads();

        // A fragments (shared across all warps)
        uint32_t aH[4][4], aL[4][4];
        #pragma unroll
        for (int mi = 0; mi < 4; mi++) {
            ldmx4(aH[mi], sb + A_OFF(b, 0) + (uint32_t)mi * 512 + aRowOff);
            ldmx4(aL[mi], sb + A_OFF(b, 1) + (uint32_t)mi * 512 + aRowOff);
        }
        #pragma unroll
        for (int nt = 0; nt < 8; nt++) {
            uint32_t bh0, bh1, bl0, bl1;
            ldmx2(bh0, bh1, sb + W_OFF(b, 0) + (uint32_t)nt * 256 + bRowOff);
            ldmx2(bl0, bl1, sb + W_OFF(b, 1) + (uint32_t)nt * 256 + bRowOff);
            #pragma unroll
            for (int mi = 0; mi < 4; mi++) {
                mma16816(c[mi][nt], aH[mi], bh0, bh1);
                mma16816(c[mi][nt], aH[mi], bl0, bl1);
                mma16816(c[mi][nt], aL[mi], bh0, bh1);
            }
        }
        __syncthreads();
    }

    // ---- epilogue: tanh, dot v, reduce ----
    const int g = lane >> 2, t4 = lane & 3;
    float p[8];
    #pragma unroll
    for (int i = 0; i < 8; i++) p[i] = 0.f;

    #pragma unroll
    for (int nt = 0; nt < 8; nt++) {
        const int a0 = wid * 64 + nt * 8 + t4 * 2;
        const float v0 = __ldg(v + a0), v1 = __ldg(v + a0 + 1);
        #pragma unroll
        for (int mi = 0; mi < 4; mi++) {
            p[mi * 2 + 0] += tanh_fast(c[mi][nt][0]) * v0 + tanh_fast(c[mi][nt][1]) * v1;
            p[mi * 2 + 1] += tanh_fast(c[mi][nt][2]) * v0 + tanh_fast(c[mi][nt][3]) * v1;
        }
    }
    #pragma unroll
    for (int i = 0; i < 8; i++) {
        p[i] += __shfl_down_sync(0xffffffffu, p[i], 1);
        p[i] += __shfl_down_sync(0xffffffffu, p[i], 2);
    }
    float* red = (float*)(smem + RED_OFF);   // [64][8]
    if (t4 == 0) {
        #pragma unroll
        for (int mi = 0; mi < 4; mi++) {
            red[(mi * 16 + g) * 8 + wid] = p[mi * 2 + 0];
            red[(mi * 16 + g + 8) * 8 + wid] = p[mi * 2 + 1];
        }
    }
    __syncthreads();
    if (tid < 64) {
        float s = 0.f;
        #pragma unroll
        for (int w = 0; w < 8; w++) s += red[tid * 8 + w];
        g_scoresT[(size_t)tid * TT + tile] = s;   // scoresT[n][t], n = row = tid
    }
}

// ---------------------------------------------------------------------------
// softmax over T per column n
// ---------------------------------------------------------------------------
__global__ void softmax_kernel(float* __restrict__ out_alpha) {
    const int n = blockIdx.x, tid = threadIdx.x;
    __shared__ float sm[256];
    const float* s = g_scoresT + (size_t)n * TT;

    float m = -1e30f;
    for (int t = tid; t < TT; t += 256) m = fmaxf(m, s[t]);
    sm[tid] = m; __syncthreads();
    #pragma unroll
    for (int o = 128; o; o >>= 1) {
        if (tid < o) sm[tid] = fmaxf(sm[tid], sm[tid + o]);
        __syncthreads();
    }
    m = sm[0];
    __syncthreads();

    float acc = 0.f;
    for (int t = tid; t < TT; t += 256) acc += expf(s[t] - m);
    sm[tid] = acc; __syncthreads();
    #pragma unroll
    for (int o = 128; o; o >>= 1) {
        if (tid < o) sm[tid] += sm[tid + o];
        __syncthreads();
    }
    const float inv = 1.0f / sm[0];

    for (int t = tid; t < TT; t += 256) {
        float al = expf(s[t] - m) * inv;
        g_alphaT[(size_t)n * TT + t] = al;
        out_alpha[(size_t)t * NN + n] = al;
    }
}

// ---------------------------------------------------------------------------
// ctx = alpha^T * enc  (partials + reduce) — already at DRAM roofline
// ---------------------------------------------------------------------------
__global__ __launch_bounds__(256) void ctx_partial_kernel(const float* __restrict__ enc) {
    const int tc = blockIdx.x & (TCH - 1);
    const int n = blockIdx.x / TCH;
    const int e0 = threadIdx.x * 4;
    float4 acc = make_float4(0.f, 0.f, 0.f, 0.f);
    const int tBeg = tc * (TT / TCH);
    #pragma unroll 4
    for (int t = tBeg; t < tBeg + TT / TCH; ++t) {
        float al = g_alphaT[(size_t)n * TT + t];
        float4 ev = *(const float4*)(enc + ((size_t)t * NN + n) * EE + e0);
        acc.x += al * ev.x; acc.y += al * ev.y;
        acc.z += al * ev.z; acc.w += al * ev.w;
    }
    *(float4*)&g_part[((size_t)tc * NN + n) * EE + e0] = acc;
}

__global__ void ctx_reduce_kernel(float* __restrict__ out_ctx) {
    const int n = blockIdx.x;
    const int e0 = threadIdx.x * 4;
    float4 acc = make_float4(0.f, 0.f, 0.f, 0.f);
    #pragma unroll
    for (int tc = 0; tc < TCH; ++tc) {
        float4 p = *(const float4*)&g_part[((size_t)tc * NN + n) * EE + e0];
        acc.x += p.x; acc.y += p.y; acc.z += p.z; acc.w += p.w;
    }
    *(float4*)&out_ctx[(size_t)n * EE + e0] = acc;
}

// ---------------------------------------------------------------------------
extern "C" void kernel_launch(void* const* d_in, const int* in_sizes, int n_in,
                              void* d_out, int out_size) {
    const float* enc = (const float*)d_in[0];   // [T, N, E]
    const float* dec = (const float*)d_in[1];   // [N, D]
    const float* We  = (const float*)d_in[2];   // [A, E]
    const float* Wd  = (const float*)d_in[3];   // [A, D]
    const float* v   = (const float*)d_in[4];   // [1, A]

    float* out = (float*)d_out;
    float* out_ctx = out;                 // [N, E]
    float* out_alpha = out + NN * EE;     // [T, N]

    static int smem_set = 0;
    if (!smem_set) {
        cudaFuncSetAttribute(scores_mma_kernel,
                             cudaFuncAttributeMaxDynamicSharedMemorySize, SMEMSZ);
        smem_set = 1;
    }

    prepW_kernel<<<(AA * EE + 255) / 256, 256>>>(We);
    dproj_kernel<<<(NN * AA) / 8, 256>>>(dec, Wd);
    scores_mma_kernel<<<TT, 256, SMEMSZ>>>(enc, v);
    softmax_kernel<<<NN, 256>>>(out_alpha);
    ctx_partial_kernel<<<NN * TCH, 256>>>(enc);
    ctx_reduce_kernel<<<NN, 256>>>(out_ctx);
}

// round 4
// speedup vs baseline: 3.8271x; 1.2607x over previous
#include <cuda_runtime.h>
#include <cuda_fp16.h>
#include <cstdint>

#define TT 2048
#define NN 64
#define EE 1024
#define DD 1024
#define AA 512
#define TCH 16

#define KSX 64      // k-steps from enc (1024/16)
#define KST 68      // + 4 one-hot k-steps carrying dproj

// ---------------- device scratch ----------------
__device__ float g_scoresT[NN * TT];
__device__ float g_alphaT[NN * TT];
__device__ float g_part[TCH * NN * EE];
__device__ __align__(16) __half g_Whi[KST * AA * 16];  // [s][a][k16]
__device__ __align__(16) __half g_Wlo[KST * AA * 16];

// ---------------- helpers ----------------
__device__ __forceinline__ uint32_t smem_u32(const void* p) {
    uint32_t a;
    asm("{ .reg .u64 t; cvta.to.shared.u64 t, %1; cvt.u32.u64 %0, t; }" : "=r"(a) : "l"(p));
    return a;
}
__device__ __forceinline__ void ldmx4(uint32_t* r, uint32_t a) {
    asm volatile("ldmatrix.sync.aligned.m8n8.x4.shared.b16 {%0,%1,%2,%3}, [%4];"
                 : "=r"(r[0]), "=r"(r[1]), "=r"(r[2]), "=r"(r[3]) : "r"(a));
}
__device__ __forceinline__ void ldmx2(uint32_t& r0, uint32_t& r1, uint32_t a) {
    asm volatile("ldmatrix.sync.aligned.m8n8.x2.shared.b16 {%0,%1}, [%2];"
                 : "=r"(r0), "=r"(r1) : "r"(a));
}
__device__ __forceinline__ void mma16816(float* d, const uint32_t* a, uint32_t b0, uint32_t b1) {
    asm volatile(
        "mma.sync.aligned.m16n8k16.row.col.f32.f16.f16.f32 "
        "{%0,%1,%2,%3}, {%4,%5,%6,%7}, {%8,%9}, {%0,%1,%2,%3};"
        : "+f"(d[0]), "+f"(d[1]), "+f"(d[2]), "+f"(d[3])
        : "r"(a[0]), "r"(a[1]), "r"(a[2]), "r"(a[3]), "r"(b0), "r"(b1));
}
__device__ __forceinline__ void cp16(uint32_t dst, const void* src) {
    asm volatile("cp.async.cg.shared.global [%0], [%1], 16;" :: "r"(dst), "l"(src) : "memory");
}
__device__ __forceinline__ void cp_commit() { asm volatile("cp.async.commit_group;" ::: "memory"); }
__device__ __forceinline__ void cp_wait1()  { asm volatile("cp.async.wait_group 1;" ::: "memory"); }
__device__ __forceinline__ void cp_wait0()  { asm volatile("cp.async.wait_group 0;" ::: "memory"); }
__device__ __forceinline__ float tanh_fast(float x) {
    float e = __expf(2.0f * x);
    return 1.0f - __fdividef(2.0f, e + 1.0f);
}

// ---------------- smem layout (bytes) ----------------
#define A_OFF(buf)    ((uint32_t)((buf) * 2048))                         // 64 rows x 32B
#define W_OFF(buf, p) ((uint32_t)(4096 + (buf) * 32768 + (p) * 16384))   // 512 rows x 32B
#define RED_OFF 69632u
#define SMEMSZ  71680

// ---------------------------------------------------------------------------
// prep: split W_e into fp16 hi/lo, k-chunked layout [s][a][k16]
// ---------------------------------------------------------------------------
__global__ void prepW_kernel(const float* __restrict__ We) {
    int i = blockIdx.x * blockDim.x + threadIdx.x;
    if (i >= AA * EE) return;
    int a = i >> 10, e = i & 1023;
    float x = We[i];
    __half hb = __float2half(x);
    float lf = x - __half2float(hb);
    int s = e >> 4, kk = e & 15;
    size_t o = ((size_t)s * AA + a) * 16 + kk;
    g_Whi[o] = hb;
    g_Wlo[o] = __float2half(lf);
}

// ---------------------------------------------------------------------------
// dproj[n][a] = dec_h[n]·W_d[a]; hi/lo into one-hot k-steps 64..67
// ---------------------------------------------------------------------------
__global__ void dproj_kernel(const float* __restrict__ dec_h,
                             const float* __restrict__ W_d) {
    int w = (blockIdx.x * blockDim.x + threadIdx.x) >> 5;
    int lane = threadIdx.x & 31;
    if (w >= NN * AA) return;
    int n = w / AA, a = w % AA;
    const float4* dh = (const float4*)(dec_h + (size_t)n * DD);
    const float4* wd = (const float4*)(W_d + (size_t)a * DD);
    float s = 0.f;
    #pragma unroll
    for (int i = lane; i < DD / 4; i += 32) {
        float4 x = dh[i], y = wd[i];
        s += x.x * y.x + x.y * y.y + x.z * y.z + x.w * y.w;
    }
    #pragma unroll
    for (int o = 16; o; o >>= 1) s += __shfl_down_sync(0xffffffffu, s, o);
    if (lane == 0) {
        __half hb = __float2half(s);
        float lf = s - __half2float(hb);
        size_t slot = ((size_t)(KSX + (n >> 4)) * AA + a) * 16 + (n & 15);
        g_Whi[slot] = hb;
        g_Wlo[slot] = __float2half(lf);
    }
}

// ---------------------------------------------------------------------------
// scores: one block per t. rows = n (64), cols = a (512).
// D = fp16(X)·(Whi+Wlo)ᵀ  (one-hot rows pull in dproj), then tanh·v reduce.
// ---------------------------------------------------------------------------
__global__ __launch_bounds__(256, 1) void scores_mma_kernel(
    const float* __restrict__ enc, const float* __restrict__ v) {
    extern __shared__ char smem[];
    const uint32_t sb = smem_u32(smem);
    const int tid = threadIdx.x;
    const int tile = blockIdx.x;
    const int lane = tid & 31;
    const int wid = tid >> 5;           // 0..7 -> a-range wid*64
    const int row = tid >> 2;           // X loader row 0..63
    const int k4 = (tid & 3) * 4;       // X loader k offset

    const size_t rowBase = ((size_t)tile * 64 + row) * EE;

    // accumulators: 4 m-frags x 8 n-tiles x 4
    float c[4][8][4] = {};

    // ---- loaders ----
    float4 xreg = *(const float4*)(enc + rowBase + k4);

    const int n0 = tid * 2;  // W copy rows (2 per thread)
    auto cpW = [&](int s, int b) {
        const char* srcH = (const char*)(g_Whi + ((size_t)s * AA + n0) * 16);
        const char* srcL = (const char*)(g_Wlo + ((size_t)s * AA + n0) * 16);
        uint32_t dH = sb + W_OFF(b, 0) + n0 * 32;
        uint32_t dL = sb + W_OFF(b, 1) + n0 * 32;
        #pragma unroll
        for (int q = 0; q < 4; q++) {
            cp16(dH + q * 16, srcH + q * 16);
            cp16(dL + q * 16, srcL + q * 16);
        }
    };

    auto stsA = [&](int s, int b) {
        unsigned short h[4];
        if (s < KSX) {
            float f[4] = {xreg.x, xreg.y, xreg.z, xreg.w};
            #pragma unroll
            for (int j = 0; j < 4; j++) {
                __half hb = __float2half(f[j]);
                h[j] = *(unsigned short*)&hb;
            }
        } else {
            #pragma unroll
            for (int j = 0; j < 4; j++) h[j] = 0;
            if ((row >> 4) == (s - KSX)) {
                int kk = (row & 15) - k4;
                if (kk >= 0 && kk < 4) h[kk] = 0x3C00;  // fp16 1.0
            }
        }
        uint2 hp;
        hp.x = ((uint32_t)h[1] << 16) | h[0]; hp.y = ((uint32_t)h[3] << 16) | h[2];
        *(uint2*)(smem + A_OFF(b) + row * 32 + k4 * 2) = hp;
    };

    // ---- ldmatrix address components ----
    const uint32_t aRowOff = (uint32_t)(lane & 15) * 32 + (uint32_t)(lane >> 4) * 16;
    const uint32_t bRowOff = (uint32_t)(wid * 64 + (lane & 7)) * 32 +
                             (uint32_t)((lane >> 3) & 1) * 16;

    // ---- prologue: W chunk 0 in flight ----
    cpW(0, 0); cp_commit();

    #pragma unroll 1
    for (int s = 0; s < KST; s++) {
        const int b = s & 1;
        stsA(s, b);
        __syncthreads();   // A-buf b written by all; all warps done with compute(s-1)
        if (s + 1 < KST) {
            if (s + 1 < KSX)
                xreg = *(const float4*)(enc + rowBase + (size_t)(s + 1) * 16 + k4);
            cpW(s + 1, b ^ 1);   // safe: all readers of W-buf b^1 (step s-1) are done
            cp_commit();
            cp_wait1();          // group for step s complete
        } else {
            cp_wait0();
        }

        // A fragments (hi only)
        uint32_t aH[4][4];
        #pragma unroll
        for (int mi = 0; mi < 4; mi++)
            ldmx4(aH[mi], sb + A_OFF(b) + (uint32_t)mi * 512 + aRowOff);

        #pragma unroll
        for (int nt = 0; nt < 8; nt++) {
            uint32_t bh0, bh1, bl0, bl1;
            ldmx2(bh0, bh1, sb + W_OFF(b, 0) + (uint32_t)nt * 256 + bRowOff);
            ldmx2(bl0, bl1, sb + W_OFF(b, 1) + (uint32_t)nt * 256 + bRowOff);
            #pragma unroll
            for (int mi = 0; mi < 4; mi++) {
                mma16816(c[mi][nt], aH[mi], bh0, bh1);
                mma16816(c[mi][nt], aH[mi], bl0, bl1);
            }
        }
    }

    // ---- epilogue: tanh, dot v, reduce ----
    const int g = lane >> 2, t4 = lane & 3;
    float p[8];
    #pragma unroll
    for (int i = 0; i < 8; i++) p[i] = 0.f;

    #pragma unroll
    for (int nt = 0; nt < 8; nt++) {
        const int a0 = wid * 64 + nt * 8 + t4 * 2;
        const float v0 = __ldg(v + a0), v1 = __ldg(v + a0 + 1);
        #pragma unroll
        for (int mi = 0; mi < 4; mi++) {
            p[mi * 2 + 0] += tanh_fast(c[mi][nt][0]) * v0 + tanh_fast(c[mi][nt][1]) * v1;
            p[mi * 2 + 1] += tanh_fast(c[mi][nt][2]) * v0 + tanh_fast(c[mi][nt][3]) * v1;
        }
    }
    #pragma unroll
    for (int i = 0; i < 8; i++) {
        p[i] += __shfl_down_sync(0xffffffffu, p[i], 1);
        p[i] += __shfl_down_sync(0xffffffffu, p[i], 2);
    }
    float* red = (float*)(smem + RED_OFF);   // [64][8]
    __syncthreads();   // compute done everywhere before reusing smem
    if (t4 == 0) {
        #pragma unroll
        for (int mi = 0; mi < 4; mi++) {
            red[(mi * 16 + g) * 8 + wid] = p[mi * 2 + 0];
            red[(mi * 16 + g + 8) * 8 + wid] = p[mi * 2 + 1];
        }
    }
    __syncthreads();
    if (tid < 64) {
        float s = 0.f;
        #pragma unroll
        for (int w = 0; w < 8; w++) s += red[tid * 8 + w];
        g_scoresT[(size_t)tid * TT + tile] = s;   // scoresT[n][t]
    }
}

// ---------------------------------------------------------------------------
// softmax over T per column n
// ---------------------------------------------------------------------------
__global__ void softmax_kernel(float* __restrict__ out_alpha) {
    const int n = blockIdx.x, tid = threadIdx.x;
    __shared__ float sm[256];
    const float* s = g_scoresT + (size_t)n * TT;

    float m = -1e30f;
    for (int t = tid; t < TT; t += 256) m = fmaxf(m, s[t]);
    sm[tid] = m; __syncthreads();
    #pragma unroll
    for (int o = 128; o; o >>= 1) {
        if (tid < o) sm[tid] = fmaxf(sm[tid], sm[tid + o]);
        __syncthreads();
    }
    m = sm[0];
    __syncthreads();

    float acc = 0.f;
    for (int t = tid; t < TT; t += 256) acc += expf(s[t] - m);
    sm[tid] = acc; __syncthreads();
    #pragma unroll
    for (int o = 128; o; o >>= 1) {
        if (tid < o) sm[tid] += sm[tid + o];
        __syncthreads();
    }
    const float inv = 1.0f / sm[0];

    for (int t = tid; t < TT; t += 256) {
        float al = expf(s[t] - m) * inv;
        g_alphaT[(size_t)n * TT + t] = al;
        out_alpha[(size_t)t * NN + n] = al;
    }
}

// ---------------------------------------------------------------------------
// ctx = alpha^T * enc  (partials + reduce) — at DRAM roofline already
// ---------------------------------------------------------------------------
__global__ __launch_bounds__(256) void ctx_partial_kernel(const float* __restrict__ enc) {
    const int tc = blockIdx.x & (TCH - 1);
    const int n = blockIdx.x / TCH;
    const int e0 = threadIdx.x * 4;
    float4 acc = make_float4(0.f, 0.f, 0.f, 0.f);
    const int tBeg = tc * (TT / TCH);
    #pragma unroll 4
    for (int t = tBeg; t < tBeg + TT / TCH; ++t) {
        float al = g_alphaT[(size_t)n * TT + t];
        float4 ev = *(const float4*)(enc + ((size_t)t * NN + n) * EE + e0);
        acc.x += al * ev.x; acc.y += al * ev.y;
        acc.z += al * ev.z; acc.w += al * ev.w;
    }
    *(float4*)&g_part[((size_t)tc * NN + n) * EE + e0] = acc;
}

__global__ void ctx_reduce_kernel(float* __restrict__ out_ctx) {
    const int n = blockIdx.x;
    const int e0 = threadIdx.x * 4;
    float4 acc = make_float4(0.f, 0.f, 0.f, 0.f);
    #pragma unroll
    for (int tc = 0; tc < TCH; ++tc) {
        float4 p = *(const float4*)&g_part[((size_t)tc * NN + n) * EE + e0];
        acc.x += p.x; acc.y += p.y; acc.z += p.z; acc.w += p.w;
    }
    *(float4*)&out_ctx[(size_t)n * EE + e0] = acc;
}

// ---------------------------------------------------------------------------
extern "C" void kernel_launch(void* const* d_in, const int* in_sizes, int n_in,
                              void* d_out, int out_size) {
    const float* enc = (const float*)d_in[0];   // [T, N, E]
    const float* dec = (const float*)d_in[1];   // [N, D]
    const float* We  = (const float*)d_in[2];   // [A, E]
    const float* Wd  = (const float*)d_in[3];   // [A, D]
    const float* v   = (const float*)d_in[4];   // [1, A]

    float* out = (float*)d_out;
    float* out_ctx = out;                 // [N, E]
    float* out_alpha = out + NN * EE;     // [T, N]

    static int smem_set = 0;
    if (!smem_set) {
        cudaFuncSetAttribute(scores_mma_kernel,
                             cudaFuncAttributeMaxDynamicSharedMemorySize, SMEMSZ);
        smem_set = 1;
    }

    prepW_kernel<<<(AA * EE + 255) / 256, 256>>>(We);
    dproj_kernel<<<(NN * AA) / 8, 256>>>(dec, Wd);
    scores_mma_kernel<<<TT, 256, SMEMSZ>>>(enc, v);
    softmax_kernel<<<NN, 256>>>(out_alpha);
    ctx_partial_kernel<<<NN * TCH, 256>>>(enc);
    ctx_reduce_kernel<<<NN, 256>>>(out_ctx);
}

// round 5
// speedup vs baseline: 4.6473x; 1.2143x over previous
#include <cuda_runtime.h>
#include <cuda_fp16.h>
#include <cstdint>

#define TT 2048
#define NN 64
#define EE 1024
#define DD 1024
#define AA 512
#define TCH 16

#define KSX 64      // k-steps from enc (1024/16)
#define KST 68      // + 4 one-hot k-steps carrying dproj

// ---------------- device scratch ----------------
__device__ float g_scoresP[2 * NN * TT];   // [half][n][t]
__device__ float g_alphaT[NN * TT];
__device__ float g_part[TCH * NN * EE];
__device__ __align__(16) __half g_Whi[KST * AA * 16];  // [s][a][k16]
__device__ __align__(16) __half g_Wlo[KST * AA * 16];

// ---------------- helpers ----------------
__device__ __forceinline__ uint32_t smem_u32(const void* p) {
    uint32_t a;
    asm("{ .reg .u64 t; cvta.to.shared.u64 t, %1; cvt.u32.u64 %0, t; }" : "=r"(a) : "l"(p));
    return a;
}
__device__ __forceinline__ void ldmx4(uint32_t* r, uint32_t a) {
    asm volatile("ldmatrix.sync.aligned.m8n8.x4.shared.b16 {%0,%1,%2,%3}, [%4];"
                 : "=r"(r[0]), "=r"(r[1]), "=r"(r[2]), "=r"(r[3]) : "r"(a));
}
__device__ __forceinline__ void mma16816(float* d, const uint32_t* a, uint32_t b0, uint32_t b1) {
    asm volatile(
        "mma.sync.aligned.m16n8k16.row.col.f32.f16.f16.f32 "
        "{%0,%1,%2,%3}, {%4,%5,%6,%7}, {%8,%9}, {%0,%1,%2,%3};"
        : "+f"(d[0]), "+f"(d[1]), "+f"(d[2]), "+f"(d[3])
        : "r"(a[0]), "r"(a[1]), "r"(a[2]), "r"(a[3]), "r"(b0), "r"(b1));
}
__device__ __forceinline__ void cp16(uint32_t dst, const void* src) {
    asm volatile("cp.async.cg.shared.global [%0], [%1], 16;" :: "r"(dst), "l"(src) : "memory");
}
__device__ __forceinline__ void cp_commit() { asm volatile("cp.async.commit_group;" ::: "memory"); }
__device__ __forceinline__ void cp_wait1()  { asm volatile("cp.async.wait_group 1;" ::: "memory"); }
__device__ __forceinline__ void cp_wait0()  { asm volatile("cp.async.wait_group 0;" ::: "memory"); }
__device__ __forceinline__ float tanh_fast(float x) {
    float e = __expf(2.0f * x);
    return 1.0f - __fdividef(2.0f, e + 1.0f);
}

// ---------------- smem layout (bytes) ----------------
#define A_OFF(buf)    ((uint32_t)((buf) * 4096))                        // 128 rows x 32B
#define W_OFF(buf, p) ((uint32_t)(8192 + (buf) * 16384 + (p) * 8192))   // 256 rows x 32B
#define RED_OFF 40960u
#define SMEMSZ  45056

// ---------------------------------------------------------------------------
// prep: split W_e into fp16 hi/lo, k-chunked layout [s][a][k16]
// ---------------------------------------------------------------------------
__global__ void prepW_kernel(const float* __restrict__ We) {
    int i = blockIdx.x * blockDim.x + threadIdx.x;
    if (i >= AA * EE) return;
    int a = i >> 10, e = i & 1023;
    float x = We[i];
    __half hb = __float2half(x);
    float lf = x - __half2float(hb);
    int s = e >> 4, kk = e & 15;
    size_t o = ((size_t)s * AA + a) * 16 + kk;
    g_Whi[o] = hb;
    g_Wlo[o] = __float2half(lf);
}

// ---------------------------------------------------------------------------
// dproj[n][a] = dec_h[n]·W_d[a]; hi/lo into one-hot k-steps 64..67
// ---------------------------------------------------------------------------
__global__ void dproj_kernel(const float* __restrict__ dec_h,
                             const float* __restrict__ W_d) {
    int w = (blockIdx.x * blockDim.x + threadIdx.x) >> 5;
    int lane = threadIdx.x & 31;
    if (w >= NN * AA) return;
    int n = w / AA, a = w % AA;
    const float4* dh = (const float4*)(dec_h + (size_t)n * DD);
    const float4* wd = (const float4*)(W_d + (size_t)a * DD);
    float s = 0.f;
    #pragma unroll
    for (int i = lane; i < DD / 4; i += 32) {
        float4 x = dh[i], y = wd[i];
        s += x.x * y.x + x.y * y.y + x.z * y.z + x.w * y.w;
    }
    #pragma unroll
    for (int o = 16; o; o >>= 1) s += __shfl_down_sync(0xffffffffu, s, o);
    if (lane == 0) {
        __half hb = __float2half(s);
        float lf = s - __half2float(hb);
        size_t slot = ((size_t)(KSX + (n >> 4)) * AA + a) * 16 + (n & 15);
        g_Whi[slot] = hb;
        g_Wlo[slot] = __float2half(lf);
    }
}

// ---------------------------------------------------------------------------
// scores: block = (t-pair, a-half). M=128 rows (2t x 64n), N=256 (a-half).
// 512 threads, 16 warps, warp-tile 64x32.
// ---------------------------------------------------------------------------
__global__ __launch_bounds__(512, 1) void scores_mma_kernel(
    const float* __restrict__ enc, const float* __restrict__ v) {
    extern __shared__ char smem[];
    const uint32_t sb = smem_u32(smem);
    const int tid = threadIdx.x;
    const int tile = blockIdx.x >> 1;       // t-pair index (0..1023)
    const int half = blockIdx.x & 1;        // a-half
    const int lane = tid & 31;
    const int wid = tid >> 5;               // 0..15
    const int mh = wid >> 3;                // m-half (0/1)
    const int ng = wid & 7;                 // n-group (32 cols each)
    const int row = tid >> 2;               // A loader row 0..127
    const int k4 = (tid & 3) * 4;           // A loader k offset
    const int aBase = half * 256;

    const size_t rowBase = ((size_t)tile * 128 + row) * EE;

    // accumulators: 4 m-frags x 4 n-tiles x 4
    float c[4][4][4] = {};

    float4 xreg = *(const float4*)(enc + rowBase + k4);

    auto cpW = [&](int s, int b) {
        // 512 threads: tid<256 -> hi rows, tid>=256 -> lo rows (256 rows x 32B each)
        int r = tid & 255;
        const __half* src = (tid < 256)
            ? (g_Whi + ((size_t)s * AA + aBase + r) * 16)
            : (g_Wlo + ((size_t)s * AA + aBase + r) * 16);
        uint32_t dst = sb + W_OFF(b, tid < 256 ? 0 : 1) + (uint32_t)r * 32;
        cp16(dst, src);
        cp16(dst + 16, (const char*)src + 16);
    };

    auto stsA = [&](int s, int b) {
        unsigned short h[4];
        if (s < KSX) {
            float f[4] = {xreg.x, xreg.y, xreg.z, xreg.w};
            #pragma unroll
            for (int j = 0; j < 4; j++) {
                __half hb = __float2half(f[j]);
                h[j] = *(unsigned short*)&hb;
            }
        } else {
            #pragma unroll
            for (int j = 0; j < 4; j++) h[j] = 0;
            int n = row & 63;
            if ((n >> 4) == (s - KSX)) {
                int kk = (n & 15) - k4;
                if (kk >= 0 && kk < 4) h[kk] = 0x3C00;  // fp16 1.0
            }
        }
        uint2 hp;
        hp.x = ((uint32_t)h[1] << 16) | h[0]; hp.y = ((uint32_t)h[3] << 16) | h[2];
        *(uint2*)(smem + A_OFF(b) + row * 32 + k4 * 2) = hp;
    };

    // ---- ldmatrix address components ----
    // A: rows mh*64 + mi*16 + (lane&15), second 16B if lane>=16
    const uint32_t aRowOff = (uint32_t)(mh * 64 + (lane & 15)) * 32 + (uint32_t)(lane >> 4) * 16;
    // B (x4 hi+lo): lanes 0-15 hi region, 16-31 lo region
    const uint32_t bRowOff = (uint32_t)(ng * 32 + (lane & 7)) * 32 +
                             (uint32_t)((lane >> 3) & 1) * 16 +
                             (uint32_t)(lane >> 4) * 8192;   // hi->lo region delta

    // ---- prologue ----
    cpW(0, 0); cp_commit();

    #pragma unroll 1
    for (int s = 0; s < KST; s++) {
        const int b = s & 1;
        stsA(s, b);
        __syncthreads();
        if (s + 1 < KST) {
            if (s + 1 < KSX)
                xreg = *(const float4*)(enc + rowBase + (size_t)(s + 1) * 16 + k4);
            cpW(s + 1, b ^ 1);
            cp_commit();
            cp_wait1();
        } else {
            cp_wait0();
        }

        uint32_t aH[4][4];
        #pragma unroll
        for (int mi = 0; mi < 4; mi++)
            ldmx4(aH[mi], sb + A_OFF(b) + (uint32_t)mi * 512 + aRowOff);

        uint32_t bf[4][4];   // [nt]: r0,r1 = hi frag, r2,r3 = lo frag
        #pragma unroll
        for (int nt = 0; nt < 4; nt++)
            ldmx4(bf[nt], sb + W_OFF(b, 0) + (uint32_t)nt * 256 + bRowOff);

        // all hi products, then all lo products (RAW distance = 16 instrs)
        #pragma unroll
        for (int nt = 0; nt < 4; nt++)
            #pragma unroll
            for (int mi = 0; mi < 4; mi++)
                mma16816(c[mi][nt], aH[mi], bf[nt][0], bf[nt][1]);
        #pragma unroll
        for (int nt = 0; nt < 4; nt++)
            #pragma unroll
            for (int mi = 0; mi < 4; mi++)
                mma16816(c[mi][nt], aH[mi], bf[nt][2], bf[nt][3]);
    }

    // ---- epilogue: tanh, dot v, reduce ----
    const int g = lane >> 2, t4 = lane & 3;
    float p[8];
    #pragma unroll
    for (int i = 0; i < 8; i++) p[i] = 0.f;

    #pragma unroll
    for (int nt = 0; nt < 4; nt++) {
        const int a0 = aBase + ng * 32 + nt * 8 + t4 * 2;
        const float v0 = __ldg(v + a0), v1 = __ldg(v + a0 + 1);
        #pragma unroll
        for (int mi = 0; mi < 4; mi++) {
            p[mi * 2 + 0] += tanh_fast(c[mi][nt][0]) * v0 + tanh_fast(c[mi][nt][1]) * v1;
            p[mi * 2 + 1] += tanh_fast(c[mi][nt][2]) * v0 + tanh_fast(c[mi][nt][3]) * v1;
        }
    }
    #pragma unroll
    for (int i = 0; i < 8; i++) {
        p[i] += __shfl_down_sync(0xffffffffu, p[i], 1);
        p[i] += __shfl_down_sync(0xffffffffu, p[i], 2);
    }
    float* red = (float*)(smem + RED_OFF);   // [128][8]
    __syncthreads();
    if (t4 == 0) {
        #pragma unroll
        for (int mi = 0; mi < 4; mi++) {
            int r0 = mh * 64 + mi * 16 + g;
            red[r0 * 8 + ng] = p[mi * 2 + 0];
            red[(r0 + 8) * 8 + ng] = p[mi * 2 + 1];
        }
    }
    __syncthreads();
    if (tid < 128) {
        float s = 0.f;
        #pragma unroll
        for (int w = 0; w < 8; w++) s += red[tid * 8 + w];
        int t = tile * 2 + (tid >> 6);
        int n = tid & 63;
        g_scoresP[(size_t)half * (NN * TT) + (size_t)n * TT + t] = s;
    }
}

// ---------------------------------------------------------------------------
// softmax over T per column n (sums the two a-half partials)
// ---------------------------------------------------------------------------
__global__ void softmax_kernel(float* __restrict__ out_alpha) {
    const int n = blockIdx.x, tid = threadIdx.x;
    __shared__ float sm[256];
    const float* s0 = g_scoresP + (size_t)n * TT;
    const float* s1 = g_scoresP + (size_t)NN * TT + (size_t)n * TT;

    float m = -1e30f;
    for (int t = tid; t < TT; t += 256) m = fmaxf(m, s0[t] + s1[t]);
    sm[tid] = m; __syncthreads();
    #pragma unroll
    for (int o = 128; o; o >>= 1) {
        if (tid < o) sm[tid] = fmaxf(sm[tid], sm[tid + o]);
        __syncthreads();
    }
    m = sm[0];
    __syncthreads();

    float acc = 0.f;
    for (int t = tid; t < TT; t += 256) acc += expf(s0[t] + s1[t] - m);
    sm[tid] = acc; __syncthreads();
    #pragma unroll
    for (int o = 128; o; o >>= 1) {
        if (tid < o) sm[tid] += sm[tid + o];
        __syncthreads();
    }
    const float inv = 1.0f / sm[0];

    for (int t = tid; t < TT; t += 256) {
        float al = expf(s0[t] + s1[t] - m) * inv;
        g_alphaT[(size_t)n * TT + t] = al;
        out_alpha[(size_t)t * NN + n] = al;
    }
}

// ---------------------------------------------------------------------------
// ctx = alpha^T * enc  (partials + reduce) — at DRAM roofline already
// ---------------------------------------------------------------------------
__global__ __launch_bounds__(256) void ctx_partial_kernel(const float* __restrict__ enc) {
    const int tc = blockIdx.x & (TCH - 1);
    const int n = blockIdx.x / TCH;
    const int e0 = threadIdx.x * 4;
    float4 acc = make_float4(0.f, 0.f, 0.f, 0.f);
    const int tBeg = tc * (TT / TCH);
    #pragma unroll 4
    for (int t = tBeg; t < tBeg + TT / TCH; ++t) {
        float al = g_alphaT[(size_t)n * TT + t];
        float4 ev = *(const float4*)(enc + ((size_t)t * NN + n) * EE + e0);
        acc.x += al * ev.x; acc.y += al * ev.y;
        acc.z += al * ev.z; acc.w += al * ev.w;
    }
    *(float4*)&g_part[((size_t)tc * NN + n) * EE + e0] = acc;
}

__global__ void ctx_reduce_kernel(float* __restrict__ out_ctx) {
    const int n = blockIdx.x;
    const int e0 = threadIdx.x * 4;
    float4 acc = make_float4(0.f, 0.f, 0.f, 0.f);
    #pragma unroll
    for (int tc = 0; tc < TCH; ++tc) {
        float4 p = *(const float4*)&g_part[((size_t)tc * NN + n) * EE + e0];
        acc.x += p.x; acc.y += p.y; acc.z += p.z; acc.w += p.w;
    }
    *(float4*)&out_ctx[(size_t)n * EE + e0] = acc;
}

// ---------------------------------------------------------------------------
extern "C" void kernel_launch(void* const* d_in, const int* in_sizes, int n_in,
                              void* d_out, int out_size) {
    const float* enc = (const float*)d_in[0];   // [T, N, E]
    const float* dec = (const float*)d_in[1];   // [N, D]
    const float* We  = (const float*)d_in[2];   // [A, E]
    const float* Wd  = (const float*)d_in[3];   // [A, D]
    const float* v   = (const float*)d_in[4];   // [1, A]

    float* out = (float*)d_out;
    float* out_ctx = out;                 // [N, E]
    float* out_alpha = out + NN * EE;     // [T, N]

    prepW_kernel<<<(AA * EE + 255) / 256, 256>>>(We);
    dproj_kernel<<<(NN * AA) / 8, 256>>>(dec, Wd);
    scores_mma_kernel<<<TT, 512, SMEMSZ>>>(enc, v);
    softmax_kernel<<<NN, 256>>>(out_alpha);
    ctx_partial_kernel<<<NN * TCH, 256>>>(enc);
    ctx_reduce_kernel<<<NN, 256>>>(out_ctx);
}

// round 6
// speedup vs baseline: 5.6543x; 1.2167x over previous
#include <cuda_runtime.h>
#include <cuda_fp16.h>
#include <cstdint>

#define TT 2048
#define NN 64
#define EE 1024
#define DD 1024
#define AA 512
#define TCH 16

#define KSX 64      // k-steps from enc (1024/16)
#define KST 68      // + 4 one-hot k-steps carrying dproj

// ---------------- device scratch ----------------
__device__ float g_scoresP[2 * NN * TT];   // [half][n][t]
__device__ float g_alphaT[NN * TT];
__device__ float g_part[TCH * NN * EE];
__device__ __align__(16) __half g_Whi[KST * AA * 16];  // [s][a][k16]
__device__ __align__(16) __half g_Wlo[KST * AA * 16];

// ---------------- helpers ----------------
__device__ __forceinline__ uint32_t smem_u32(const void* p) {
    uint32_t a;
    asm("{ .reg .u64 t; cvta.to.shared.u64 t, %1; cvt.u32.u64 %0, t; }" : "=r"(a) : "l"(p));
    return a;
}
__device__ __forceinline__ void ldmx4(uint32_t* r, uint32_t a) {
    asm volatile("ldmatrix.sync.aligned.m8n8.x4.shared.b16 {%0,%1,%2,%3}, [%4];"
                 : "=r"(r[0]), "=r"(r[1]), "=r"(r[2]), "=r"(r[3]) : "r"(a));
}
__device__ __forceinline__ void ldmx2(uint32_t& r0, uint32_t& r1, uint32_t a) {
    asm volatile("ldmatrix.sync.aligned.m8n8.x2.shared.b16 {%0,%1}, [%2];"
                 : "=r"(r0), "=r"(r1) : "r"(a));
}
__device__ __forceinline__ void mma16816(float* d, const uint32_t* a, uint32_t b0, uint32_t b1) {
    asm volatile(
        "mma.sync.aligned.m16n8k16.row.col.f32.f16.f16.f32 "
        "{%0,%1,%2,%3}, {%4,%5,%6,%7}, {%8,%9}, {%0,%1,%2,%3};"
        : "+f"(d[0]), "+f"(d[1]), "+f"(d[2]), "+f"(d[3])
        : "r"(a[0]), "r"(a[1]), "r"(a[2]), "r"(a[3]), "r"(b0), "r"(b1));
}
__device__ __forceinline__ void cp16(uint32_t dst, const void* src) {
    asm volatile("cp.async.cg.shared.global [%0], [%1], 16;" :: "r"(dst), "l"(src) : "memory");
}
__device__ __forceinline__ void cp_commit() { asm volatile("cp.async.commit_group;" ::: "memory"); }
__device__ __forceinline__ void cp_wait1()  { asm volatile("cp.async.wait_group 1;" ::: "memory"); }
__device__ __forceinline__ void cp_wait0()  { asm volatile("cp.async.wait_group 0;" ::: "memory"); }
__device__ __forceinline__ float tanh_fast(float x) {
    float e = __expf(2.0f * x);
    return 1.0f - __fdividef(2.0f, e + 1.0f);
}

// ---------------- smem layout (bytes) ----------------
#define A_OFF(buf)    ((uint32_t)((buf) * 4096))                        // 128 rows x 32B
#define W_OFF(buf, p) ((uint32_t)(8192 + (buf) * 16384 + (p) * 8192))   // 256 rows x 32B
#define RED_OFF 40960u
#define SMEMSZ  45056

// ---------------------------------------------------------------------------
// prep: split W_e into fp16 hi/lo, k-chunked layout [s][a][k16]
// ---------------------------------------------------------------------------
__global__ void prepW_kernel(const float* __restrict__ We) {
    int i = blockIdx.x * blockDim.x + threadIdx.x;
    if (i >= AA * EE) return;
    int a = i >> 10, e = i & 1023;
    float x = We[i];
    __half hb = __float2half(x);
    float lf = x - __half2float(hb);
    int s = e >> 4, kk = e & 15;
    size_t o = ((size_t)s * AA + a) * 16 + kk;
    g_Whi[o] = hb;
    g_Wlo[o] = __float2half(lf);
}

// ---------------------------------------------------------------------------
// dproj[n][a] = dec_h[n]·W_d[a]; hi/lo into one-hot k-steps 64..67
// ---------------------------------------------------------------------------
__global__ void dproj_kernel(const float* __restrict__ dec_h,
                             const float* __restrict__ W_d) {
    int w = (blockIdx.x * blockDim.x + threadIdx.x) >> 5;
    int lane = threadIdx.x & 31;
    if (w >= NN * AA) return;
    int n = w / AA, a = w % AA;
    const float4* dh = (const float4*)(dec_h + (size_t)n * DD);
    const float4* wd = (const float4*)(W_d + (size_t)a * DD);
    float s = 0.f;
    #pragma unroll
    for (int i = lane; i < DD / 4; i += 32) {
        float4 x = dh[i], y = wd[i];
        s += x.x * y.x + x.y * y.y + x.z * y.z + x.w * y.w;
    }
    #pragma unroll
    for (int o = 16; o; o >>= 1) s += __shfl_down_sync(0xffffffffu, s, o);
    if (lane == 0) {
        __half hb = __float2half(s);
        float lf = s - __half2float(hb);
        size_t slot = ((size_t)(KSX + (n >> 4)) * AA + a) * 16 + (n & 15);
        g_Whi[slot] = hb;
        g_Wlo[slot] = __float2half(lf);
    }
}

// ---------------------------------------------------------------------------
// scores: block = (t-pair, a-half). M=128 rows (2t x 64n), N=256 (a-half).
// 512 threads, 16 warps, warp-tile 64x32. Single fp16 product for main K;
// hi+lo products only for the 4 one-hot dproj k-steps.
// ---------------------------------------------------------------------------
__global__ __launch_bounds__(512, 1) void scores_mma_kernel(
    const float* __restrict__ enc, const float* __restrict__ v) {
    extern __shared__ char smem[];
    const uint32_t sb = smem_u32(smem);
    const int tid = threadIdx.x;
    const int tile = blockIdx.x >> 1;       // t-pair index (0..1023)
    const int half = blockIdx.x & 1;        // a-half
    const int lane = tid & 31;
    const int wid = tid >> 5;               // 0..15
    const int mh = wid >> 3;                // m-half (0/1)
    const int ng = wid & 7;                 // n-group (32 cols each)
    const int row = tid >> 2;               // A loader row 0..127
    const int k4 = (tid & 3) * 4;           // A loader k offset
    const int aBase = half * 256;

    const size_t rowBase = ((size_t)tile * 128 + row) * EE;

    // accumulators: 4 m-frags x 4 n-tiles x 4
    float c[4][4][4] = {};

    float4 xreg = *(const float4*)(enc + rowBase + k4);

    auto cpW = [&](int s, int b) {
        int r = tid & 255;
        if (tid < 256) {
            const __half* src = g_Whi + ((size_t)s * AA + aBase + r) * 16;
            uint32_t dst = sb + W_OFF(b, 0) + (uint32_t)r * 32;
            cp16(dst, src);
            cp16(dst + 16, src + 8);
        } else if (s >= KSX) {     // lo needed only for one-hot dproj steps
            const __half* src = g_Wlo + ((size_t)s * AA + aBase + r) * 16;
            uint32_t dst = sb + W_OFF(b, 1) + (uint32_t)r * 32;
            cp16(dst, src);
            cp16(dst + 16, src + 8);
        }
    };

    auto stsA = [&](int s, int b) {
        unsigned short h[4];
        if (s < KSX) {
            float f[4] = {xreg.x, xreg.y, xreg.z, xreg.w};
            #pragma unroll
            for (int j = 0; j < 4; j++) {
                __half hb = __float2half(f[j]);
                h[j] = *(unsigned short*)&hb;
            }
        } else {
            #pragma unroll
            for (int j = 0; j < 4; j++) h[j] = 0;
            int n = row & 63;
            if ((n >> 4) == (s - KSX)) {
                int kk = (n & 15) - k4;
                if (kk >= 0 && kk < 4) h[kk] = 0x3C00;  // fp16 1.0
            }
        }
        uint2 hp;
        hp.x = ((uint32_t)h[1] << 16) | h[0]; hp.y = ((uint32_t)h[3] << 16) | h[2];
        *(uint2*)(smem + A_OFF(b) + row * 32 + k4 * 2) = hp;
    };

    // ---- ldmatrix address components ----
    const uint32_t aRowOff = (uint32_t)(mh * 64 + (lane & 15)) * 32 + (uint32_t)(lane >> 4) * 16;
    // x2 uses lanes 0-15 (hi frag); x4 adds lanes 16-31 -> lo region (+8192)
    const uint32_t bRowOff = (uint32_t)(ng * 32 + (lane & 7)) * 32 +
                             (uint32_t)((lane >> 3) & 1) * 16 +
                             (uint32_t)(lane >> 4) * 8192;

    // ---- prologue ----
    cpW(0, 0); cp_commit();

    #pragma unroll 1
    for (int s = 0; s < KST; s++) {
        const int b = s & 1;
        stsA(s, b);
        __syncthreads();
        if (s + 1 < KST) {
            if (s + 1 < KSX)
                xreg = *(const float4*)(enc + rowBase + (size_t)(s + 1) * 16 + k4);
            cpW(s + 1, b ^ 1);
            cp_commit();
            cp_wait1();
        } else {
            cp_wait0();
        }

        uint32_t aH[4][4];
        #pragma unroll
        for (int mi = 0; mi < 4; mi++)
            ldmx4(aH[mi], sb + A_OFF(b) + (uint32_t)mi * 512 + aRowOff);

        if (s < KSX) {
            // single product: X_h · W_h
            uint32_t bh[4][2];
            #pragma unroll
            for (int nt = 0; nt < 4; nt++)
                ldmx2(bh[nt][0], bh[nt][1], sb + W_OFF(b, 0) + (uint32_t)nt * 256 + bRowOff);
            #pragma unroll
            for (int nt = 0; nt < 4; nt++)
                #pragma unroll
                for (int mi = 0; mi < 4; mi++)
                    mma16816(c[mi][nt], aH[mi], bh[nt][0], bh[nt][1]);
        } else {
            // one-hot dproj steps: hi + lo products (keeps dproj ~fp32 exact)
            uint32_t bf[4][4];
            #pragma unroll
            for (int nt = 0; nt < 4; nt++)
                ldmx4(bf[nt], sb + W_OFF(b, 0) + (uint32_t)nt * 256 + bRowOff);
            #pragma unroll
            for (int nt = 0; nt < 4; nt++)
                #pragma unroll
                for (int mi = 0; mi < 4; mi++)
                    mma16816(c[mi][nt], aH[mi], bf[nt][0], bf[nt][1]);
            #pragma unroll
            for (int nt = 0; nt < 4; nt++)
                #pragma unroll
                for (int mi = 0; mi < 4; mi++)
                    mma16816(c[mi][nt], aH[mi], bf[nt][2], bf[nt][3]);
        }
    }

    // ---- epilogue: tanh, dot v, reduce ----
    const int g = lane >> 2, t4 = lane & 3;
    float p[8];
    #pragma unroll
    for (int i = 0; i < 8; i++) p[i] = 0.f;

    #pragma unroll
    for (int nt = 0; nt < 4; nt++) {
        const int a0 = aBase + ng * 32 + nt * 8 + t4 * 2;
        const float v0 = __ldg(v + a0), v1 = __ldg(v + a0 + 1);
        #pragma unroll
        for (int mi = 0; mi < 4; mi++) {
            p[mi * 2 + 0] += tanh_fast(c[mi][nt][0]) * v0 + tanh_fast(c[mi][nt][1]) * v1;
            p[mi * 2 + 1] += tanh_fast(c[mi][nt][2]) * v0 + tanh_fast(c[mi][nt][3]) * v1;
        }
    }
    #pragma unroll
    for (int i = 0; i < 8; i++) {
        p[i] += __shfl_down_sync(0xffffffffu, p[i], 1);
        p[i] += __shfl_down_sync(0xffffffffu, p[i], 2);
    }
    float* red = (float*)(smem + RED_OFF);   // [128][8]
    __syncthreads();
    if (t4 == 0) {
        #pragma unroll
        for (int mi = 0; mi < 4; mi++) {
            int r0 = mh * 64 + mi * 16 + g;
            red[r0 * 8 + ng] = p[mi * 2 + 0];
            red[(r0 + 8) * 8 + ng] = p[mi * 2 + 1];
        }
    }
    __syncthreads();
    if (tid < 128) {
        float s = 0.f;
        #pragma unroll
        for (int w = 0; w < 8; w++) s += red[tid * 8 + w];
        int t = tile * 2 + (tid >> 6);
        int n = tid & 63;
        g_scoresP[(size_t)half * (NN * TT) + (size_t)n * TT + t] = s;
    }
}

// ---------------------------------------------------------------------------
// softmax over T per column n (sums the two a-half partials)
// ---------------------------------------------------------------------------
__global__ void softmax_kernel(float* __restrict__ out_alpha) {
    const int n = blockIdx.x, tid = threadIdx.x;
    __shared__ float sm[256];
    const float* s0 = g_scoresP + (size_t)n * TT;
    const float* s1 = g_scoresP + (size_t)NN * TT + (size_t)n * TT;

    float m = -1e30f;
    for (int t = tid; t < TT; t += 256) m = fmaxf(m, s0[t] + s1[t]);
    sm[tid] = m; __syncthreads();
    #pragma unroll
    for (int o = 128; o; o >>= 1) {
        if (tid < o) sm[tid] = fmaxf(sm[tid], sm[tid + o]);
        __syncthreads();
    }
    m = sm[0];
    __syncthreads();

    float acc = 0.f;
    for (int t = tid; t < TT; t += 256) acc += expf(s0[t] + s1[t] - m);
    sm[tid] = acc; __syncthreads();
    #pragma unroll
    for (int o = 128; o; o >>= 1) {
        if (tid < o) sm[tid] += sm[tid + o];
        __syncthreads();
    }
    const float inv = 1.0f / sm[0];

    for (int t = tid; t < TT; t += 256) {
        float al = expf(s0[t] + s1[t] - m) * inv;
        g_alphaT[(size_t)n * TT + t] = al;
        out_alpha[(size_t)t * NN + n] = al;
    }
}

// ---------------------------------------------------------------------------
// ctx = alpha^T * enc  (partials + reduce) — at DRAM roofline already
// ---------------------------------------------------------------------------
__global__ __launch_bounds__(256) void ctx_partial_kernel(const float* __restrict__ enc) {
    const int tc = blockIdx.x & (TCH - 1);
    const int n = blockIdx.x / TCH;
    const int e0 = threadIdx.x * 4;
    float4 acc = make_float4(0.f, 0.f, 0.f, 0.f);
    const int tBeg = tc * (TT / TCH);
    #pragma unroll 4
    for (int t = tBeg; t < tBeg + TT / TCH; ++t) {
        float al = g_alphaT[(size_t)n * TT + t];
        float4 ev = *(const float4*)(enc + ((size_t)t * NN + n) * EE + e0);
        acc.x += al * ev.x; acc.y += al * ev.y;
        acc.z += al * ev.z; acc.w += al * ev.w;
    }
    *(float4*)&g_part[((size_t)tc * NN + n) * EE + e0] = acc;
}

__global__ void ctx_reduce_kernel(float* __restrict__ out_ctx) {
    const int n = blockIdx.x;
    const int e0 = threadIdx.x * 4;
    float4 acc = make_float4(0.f, 0.f, 0.f, 0.f);
    #pragma unroll
    for (int tc = 0; tc < TCH; ++tc) {
        float4 p = *(const float4*)&g_part[((size_t)tc * NN + n) * EE + e0];
        acc.x += p.x; acc.y += p.y; acc.z += p.z; acc.w += p.w;
    }
    *(float4*)&out_ctx[(size_t)n * EE + e0] = acc;
}

// ---------------------------------------------------------------------------
extern "C" void kernel_launch(void* const* d_in, const int* in_sizes, int n_in,
                              void* d_out, int out_size) {
    const float* enc = (const float*)d_in[0];   // [T, N, E]
    const float* dec = (const float*)d_in[1];   // [N, D]
    const float* We  = (const float*)d_in[2];   // [A, E]
    const float* Wd  = (const float*)d_in[3];   // [A, D]
    const float* v   = (const float*)d_in[4];   // [1, A]

    float* out = (float*)d_out;
    float* out_ctx = out;                 // [N, E]
    float* out_alpha = out + NN * EE;     // [T, N]

    prepW_kernel<<<(AA * EE + 255) / 256, 256>>>(We);
    dproj_kernel<<<(NN * AA) / 8, 256>>>(dec, Wd);
    scores_mma_kernel<<<TT, 512, SMEMSZ>>>(enc, v);
    softmax_kernel<<<NN, 256>>>(out_alpha);
    ctx_partial_kernel<<<NN * TCH, 256>>>(enc);
    ctx_reduce_kernel<<<NN, 256>>>(out_ctx);
}

// round 7
// speedup vs baseline: 6.8580x; 1.2129x over previous
#include <cuda_runtime.h>
#include <cuda_fp16.h>
#include <cstdint>

#define TT 2048
#define NN 64
#define EE 1024
#define DD 1024
#define AA 512
#define TCH 16

#define KSX 64      // 16-wide k-steps from enc (1024/16)
#define NIT 32      // loop iterations (32 K per iteration)

// ---------------- device scratch ----------------
__device__ float g_scoresP[2 * NN * TT];   // [half][n][t]
__device__ float g_alphaT[NN * TT];
__device__ float g_part[TCH * NN * EE];
__device__ float g_dproj[NN * AA];         // [n][a] fp32, exact
__device__ __align__(16) __half g_Whi[KSX * AA * 16];  // [s][a][k16]

// ---------------- helpers ----------------
__device__ __forceinline__ uint32_t smem_u32(const void* p) {
    uint32_t a;
    asm("{ .reg .u64 t; cvta.to.shared.u64 t, %1; cvt.u32.u64 %0, t; }" : "=r"(a) : "l"(p));
    return a;
}
__device__ __forceinline__ void ldmx4(uint32_t* r, uint32_t a) {
    asm volatile("ldmatrix.sync.aligned.m8n8.x4.shared.b16 {%0,%1,%2,%3}, [%4];"
                 : "=r"(r[0]), "=r"(r[1]), "=r"(r[2]), "=r"(r[3]) : "r"(a));
}
__device__ __forceinline__ void ldmx2(uint32_t& r0, uint32_t& r1, uint32_t a) {
    asm volatile("ldmatrix.sync.aligned.m8n8.x2.shared.b16 {%0,%1}, [%2];"
                 : "=r"(r0), "=r"(r1) : "r"(a));
}
__device__ __forceinline__ void mma16816(float* d, const uint32_t* a, uint32_t b0, uint32_t b1) {
    asm volatile(
        "mma.sync.aligned.m16n8k16.row.col.f32.f16.f16.f32 "
        "{%0,%1,%2,%3}, {%4,%5,%6,%7}, {%8,%9}, {%0,%1,%2,%3};"
        : "+f"(d[0]), "+f"(d[1]), "+f"(d[2]), "+f"(d[3])
        : "r"(a[0]), "r"(a[1]), "r"(a[2]), "r"(a[3]), "r"(b0), "r"(b1));
}
__device__ __forceinline__ void cp16(uint32_t dst, const void* src) {
    asm volatile("cp.async.cg.shared.global [%0], [%1], 16;" :: "r"(dst), "l"(src) : "memory");
}
__device__ __forceinline__ void cp_commit() { asm volatile("cp.async.commit_group;" ::: "memory"); }
__device__ __forceinline__ void cp_wait0()  { asm volatile("cp.async.wait_group 0;" ::: "memory"); }
__device__ __forceinline__ float tanh_fast(float x) {
    float e = __expf(2.0f * x);
    return 1.0f - __fdividef(2.0f, e + 1.0f);
}

// ---------------- smem layout (bytes), total exactly 48KB ----------------
#define A_OFF(buf)  ((uint32_t)((buf) * 8192))            // 2 x (2 panels x 4KB)
#define W_OFF(buf)  ((uint32_t)(16384 + (buf) * 16384))   // 2 x (2 panels x 8KB)
#define RED_OFF 0u                                        // reuses A region post-loop
#define SMEMSZ  49152

// ---------------------------------------------------------------------------
// prep: fp16 hi of W_e, k-chunked layout [s][a][k16]
// ---------------------------------------------------------------------------
__global__ void prepW_kernel(const float* __restrict__ We) {
    int i = blockIdx.x * blockDim.x + threadIdx.x;
    if (i >= AA * EE) return;
    int a = i >> 10, e = i & 1023;
    int s = e >> 4, kk = e & 15;
    g_Whi[((size_t)s * AA + a) * 16 + kk] = __float2half(We[i]);
}

// ---------------------------------------------------------------------------
// dproj[n][a] = dec_h[n]·W_d[a]  (exact fp32, consumed in scores epilogue)
// ---------------------------------------------------------------------------
__global__ void dproj_kernel(const float* __restrict__ dec_h,
                             const float* __restrict__ W_d) {
    int w = (blockIdx.x * blockDim.x + threadIdx.x) >> 5;
    int lane = threadIdx.x & 31;
    if (w >= NN * AA) return;
    int n = w / AA, a = w % AA;
    const float4* dh = (const float4*)(dec_h + (size_t)n * DD);
    const float4* wd = (const float4*)(W_d + (size_t)a * DD);
    float s = 0.f;
    #pragma unroll
    for (int i = lane; i < DD / 4; i += 32) {
        float4 x = dh[i], y = wd[i];
        s += x.x * y.x + x.y * y.y + x.z * y.z + x.w * y.w;
    }
    #pragma unroll
    for (int o = 16; o; o >>= 1) s += __shfl_down_sync(0xffffffffu, s, o);
    if (lane == 0) g_dproj[n * AA + a] = s;
}

// ---------------------------------------------------------------------------
// scores: block = (t-pair, a-half). M=128 (2t x 64n), N=256 (a-half), K=32/iter.
// 512 threads, 16 warps, warp-tile 64x32. Single fp16 product; dproj in epilogue.
// ---------------------------------------------------------------------------
__global__ __launch_bounds__(512, 1) void scores_mma_kernel(
    const float* __restrict__ enc, const float* __restrict__ v) {
    extern __shared__ char smem[];
    const uint32_t sb = smem_u32(smem);
    const int tid = threadIdx.x;
    const int tile = blockIdx.x >> 1;       // t-pair (0..1023)
    const int half = blockIdx.x & 1;        // a-half
    const int lane = tid & 31;
    const int wid = tid >> 5;               // 0..15
    const int mh = wid >> 3;                // m-half
    const int ng = wid & 7;                 // n-group (32 cols)
    const int row = tid >> 2;               // A loader row 0..127
    const int k4 = (tid & 3) * 4;           // A loader k offset
    const int aBase = half * 256;

    const size_t rowBase = ((size_t)tile * 128 + row) * EE;

    float c[4][4][4] = {};

    // W copy: thread -> (panel, row)
    const int wsub = tid >= 256;
    const int wr = tid & 255;
    auto cpW = [&](int i, int b) {
        const __half* src = g_Whi + ((size_t)(2 * i + wsub) * AA + aBase + wr) * 16;
        uint32_t dst = sb + W_OFF(b) + (uint32_t)wsub * 8192 + (uint32_t)wr * 32;
        cp16(dst, src);
        cp16(dst + 16, src + 8);
    };

    auto stsA = [&](int b, float4 x0, float4 x1) {
        #pragma unroll
        for (int sub = 0; sub < 2; sub++) {
            float f[4];
            if (sub == 0) { f[0] = x0.x; f[1] = x0.y; f[2] = x0.z; f[3] = x0.w; }
            else          { f[0] = x1.x; f[1] = x1.y; f[2] = x1.z; f[3] = x1.w; }
            unsigned short h[4];
            #pragma unroll
            for (int j = 0; j < 4; j++) {
                __half hb = __float2half(f[j]);
                h[j] = *(unsigned short*)&hb;
            }
            uint2 hp;
            hp.x = ((uint32_t)h[1] << 16) | h[0];
            hp.y = ((uint32_t)h[3] << 16) | h[2];
            *(uint2*)(smem + A_OFF(b) + sub * 4096 + row * 32 + k4 * 2) = hp;
        }
    };

    // ldmatrix address components
    const uint32_t aRowOff = (uint32_t)(mh * 64 + (lane & 15)) * 32 + (uint32_t)(lane >> 4) * 16;
    const uint32_t bRowOff = (uint32_t)(ng * 32 + (lane & 7)) * 32 + (uint32_t)((lane >> 3) & 1) * 16;

    // ---- prologue ----
    cpW(0, 0); cp_commit();
    float4 x0 = *(const float4*)(enc + rowBase + k4);
    float4 x1 = *(const float4*)(enc + rowBase + 16 + k4);

    #pragma unroll 1
    for (int i = 0; i < NIT; i++) {
        const int b = i & 1;
        stsA(b, x0, x1);
        cp_wait0();        // this thread's W(i) copies done
        __syncthreads();   // everyone's W(i) + A stores visible
        if (i + 1 < NIT) {
            x0 = *(const float4*)(enc + rowBase + (size_t)(i + 1) * 32 + k4);
            x1 = *(const float4*)(enc + rowBase + (size_t)(i + 1) * 32 + 16 + k4);
            cpW(i + 1, b ^ 1);   // readers of buf b^1 finished before the barrier above
            cp_commit();
        }

        #pragma unroll
        for (int sub = 0; sub < 2; sub++) {
            uint32_t aH[4][4];
            #pragma unroll
            for (int mi = 0; mi < 4; mi++)
                ldmx4(aH[mi], sb + A_OFF(b) + (uint32_t)sub * 4096 + (uint32_t)mi * 512 + aRowOff);
            uint32_t bh[4][2];
            #pragma unroll
            for (int nt = 0; nt < 4; nt++)
                ldmx2(bh[nt][0], bh[nt][1],
                      sb + W_OFF(b) + (uint32_t)sub * 8192 + (uint32_t)nt * 256 + bRowOff);
            #pragma unroll
            for (int nt = 0; nt < 4; nt++)
                #pragma unroll
                for (int mi = 0; mi < 4; mi++)
                    mma16816(c[mi][nt], aH[mi], bh[nt][0], bh[nt][1]);
        }
    }

    // ---- epilogue: + dproj (exact fp32), tanh, dot v, reduce ----
    const int g = lane >> 2, t4 = lane & 3;
    float p[8];
    #pragma unroll
    for (int i = 0; i < 8; i++) p[i] = 0.f;

    #pragma unroll
    for (int nt = 0; nt < 4; nt++) {
        const int a0 = aBase + ng * 32 + nt * 8 + t4 * 2;
        const float v0 = __ldg(v + a0), v1 = __ldg(v + a0 + 1);
        #pragma unroll
        for (int mi = 0; mi < 4; mi++) {
            const int n0 = mi * 16 + g;
            float2 d0 = *(const float2*)(g_dproj + (size_t)n0 * AA + a0);
            float2 d1 = *(const float2*)(g_dproj + (size_t)(n0 + 8) * AA + a0);
            p[mi * 2 + 0] += tanh_fast(c[mi][nt][0] + d0.x) * v0 +
                             tanh_fast(c[mi][nt][1] + d0.y) * v1;
            p[mi * 2 + 1] += tanh_fast(c[mi][nt][2] + d1.x) * v0 +
                             tanh_fast(c[mi][nt][3] + d1.y) * v1;
        }
    }
    #pragma unroll
    for (int i = 0; i < 8; i++) {
        p[i] += __shfl_down_sync(0xffffffffu, p[i], 1);
        p[i] += __shfl_down_sync(0xffffffffu, p[i], 2);
    }
    float* red = (float*)(smem + RED_OFF);   // [128][8], reuses A region
    __syncthreads();
    if (t4 == 0) {
        #pragma unroll
        for (int mi = 0; mi < 4; mi++) {
            int r0 = mh * 64 + mi * 16 + g;
            red[r0 * 8 + ng] = p[mi * 2 + 0];
            red[(r0 + 8) * 8 + ng] = p[mi * 2 + 1];
        }
    }
    __syncthreads();
    if (tid < 128) {
        float s = 0.f;
        #pragma unroll
        for (int w = 0; w < 8; w++) s += red[tid * 8 + w];
        int t = tile * 2 + (tid >> 6);
        int n = tid & 63;
        g_scoresP[(size_t)half * (NN * TT) + (size_t)n * TT + t] = s;
    }
}

// ---------------------------------------------------------------------------
// softmax over T per column n (sums the two a-half partials)
// ---------------------------------------------------------------------------
__global__ void softmax_kernel(float* __restrict__ out_alpha) {
    const int n = blockIdx.x, tid = threadIdx.x;
    __shared__ float sm[256];
    const float* s0 = g_scoresP + (size_t)n * TT;
    const float* s1 = g_scoresP + (size_t)NN * TT + (size_t)n * TT;

    float m = -1e30f;
    for (int t = tid; t < TT; t += 256) m = fmaxf(m, s0[t] + s1[t]);
    sm[tid] = m; __syncthreads();
    #pragma unroll
    for (int o = 128; o; o >>= 1) {
        if (tid < o) sm[tid] = fmaxf(sm[tid], sm[tid + o]);
        __syncthreads();
    }
    m = sm[0];
    __syncthreads();

    float acc = 0.f;
    for (int t = tid; t < TT; t += 256) acc += expf(s0[t] + s1[t] - m);
    sm[tid] = acc; __syncthreads();
    #pragma unroll
    for (int o = 128; o; o >>= 1) {
        if (tid < o) sm[tid] += sm[tid + o];
        __syncthreads();
    }
    const float inv = 1.0f / sm[0];

    for (int t = tid; t < TT; t += 256) {
        float al = expf(s0[t] + s1[t] - m) * inv;
        g_alphaT[(size_t)n * TT + t] = al;
        out_alpha[(size_t)t * NN + n] = al;
    }
}

// ---------------------------------------------------------------------------
// ctx = alpha^T * enc  (partials + reduce) — at DRAM roofline already
// ---------------------------------------------------------------------------
__global__ __launch_bounds__(256) void ctx_partial_kernel(const float* __restrict__ enc) {
    const int tc = blockIdx.x & (TCH - 1);
    const int n = blockIdx.x / TCH;
    const int e0 = threadIdx.x * 4;
    float4 acc = make_float4(0.f, 0.f, 0.f, 0.f);
    const int tBeg = tc * (TT / TCH);
    #pragma unroll 4
    for (int t = tBeg; t < tBeg + TT / TCH; ++t) {
        float al = g_alphaT[(size_t)n * TT + t];
        float4 ev = *(const float4*)(enc + ((size_t)t * NN + n) * EE + e0);
        acc.x += al * ev.x; acc.y += al * ev.y;
        acc.z += al * ev.z; acc.w += al * ev.w;
    }
    *(float4*)&g_part[((size_t)tc * NN + n) * EE + e0] = acc;
}

__global__ void ctx_reduce_kernel(float* __restrict__ out_ctx) {
    const int n = blockIdx.x;
    const int e0 = threadIdx.x * 4;
    float4 acc = make_float4(0.f, 0.f, 0.f, 0.f);
    #pragma unroll
    for (int tc = 0; tc < TCH; ++tc) {
        float4 p = *(const float4*)&g_part[((size_t)tc * NN + n) * EE + e0];
        acc.x += p.x; acc.y += p.y; acc.z += p.z; acc.w += p.w;
    }
    *(float4*)&out_ctx[(size_t)n * EE + e0] = acc;
}

// ---------------------------------------------------------------------------
extern "C" void kernel_launch(void* const* d_in, const int* in_sizes, int n_in,
                              void* d_out, int out_size) {
    const float* enc = (const float*)d_in[0];   // [T, N, E]
    const float* dec = (const float*)d_in[1];   // [N, D]
    const float* We  = (const float*)d_in[2];   // [A, E]
    const float* Wd  = (const float*)d_in[3];   // [A, D]
    const float* v   = (const float*)d_in[4];   // [1, A]

    float* out = (float*)d_out;
    float* out_ctx = out;                 // [N, E]
    float* out_alpha = out + NN * EE;     // [T, N]

    prepW_kernel<<<(AA * EE + 255) / 256, 256>>>(We);
    dproj_kernel<<<(NN * AA) / 8, 256>>>(dec, Wd);
    scores_mma_kernel<<<TT, 512, SMEMSZ>>>(enc, v);
    softmax_kernel<<<NN, 256>>>(out_alpha);
    ctx_partial_kernel<<<NN * TCH, 256>>>(enc);
    ctx_reduce_kernel<<<NN, 256>>>(out_ctx);
}

// round 8
// speedup vs baseline: 8.2145x; 1.1978x over previous
#include <cuda_runtime.h>
#include <cuda_fp16.h>
#include <cstdint>

#define TT 2048
#define NN 64
#define EE 1024
#define DD 1024
#define AA 512
#define TCH 16

#define NIT 32      // K=32 per iteration

// ---------------- device scratch ----------------
__device__ float g_scoresP[2 * NN * TT];   // [half][n][t]
__device__ float g_alphaT[NN * TT];
__device__ float g_part[TCH * NN * EE];
__device__ float g_dproj[NN * AA];         // [n][a] fp32, exact
__device__ __align__(16) __half g_W16[64 * 2 * AA * 8];  // [s][chunk][a][8]

// ---------------- helpers ----------------
__device__ __forceinline__ uint32_t smem_u32(const void* p) {
    uint32_t a;
    asm("{ .reg .u64 t; cvta.to.shared.u64 t, %1; cvt.u32.u64 %0, t; }" : "=r"(a) : "l"(p));
    return a;
}
__device__ __forceinline__ void ldmx4(uint32_t* r, uint32_t a) {
    asm volatile("ldmatrix.sync.aligned.m8n8.x4.shared.b16 {%0,%1,%2,%3}, [%4];"
                 : "=r"(r[0]), "=r"(r[1]), "=r"(r[2]), "=r"(r[3]) : "r"(a));
}
__device__ __forceinline__ void mma16816(float* d, const uint32_t* a, uint32_t b0, uint32_t b1) {
    asm volatile(
        "mma.sync.aligned.m16n8k16.row.col.f32.f16.f16.f32 "
        "{%0,%1,%2,%3}, {%4,%5,%6,%7}, {%8,%9}, {%0,%1,%2,%3};"
        : "+f"(d[0]), "+f"(d[1]), "+f"(d[2]), "+f"(d[3])
        : "r"(a[0]), "r"(a[1]), "r"(a[2]), "r"(a[3]), "r"(b0), "r"(b1));
}
__device__ __forceinline__ void cp16(uint32_t dst, const void* src) {
    asm volatile("cp.async.cg.shared.global [%0], [%1], 16;" :: "r"(dst), "l"(src) : "memory");
}
__device__ __forceinline__ void cp_commit() { asm volatile("cp.async.commit_group;" ::: "memory"); }
__device__ __forceinline__ void cp_wait0()  { asm volatile("cp.async.wait_group 0;" ::: "memory"); }
__device__ __forceinline__ float tanh_fast(float x) {
    float e = __expf(2.0f * x);
    return 1.0f - __fdividef(2.0f, e + 1.0f);
}

// ---------------- smem layout (bytes), 48KB total ----------------
// A buf: [panel(2)][chunk(2)][row(128)][16B] = 8KB ; addr = p*4096 + c*2048 + r*16
#define A_OFF(buf)  ((uint32_t)((buf) * 8192))
// W buf: [panel(2)][chunk(2)][row(256)][16B] = 16KB ; addr = p*8192 + c*4096 + r*16
#define W_OFF(buf)  ((uint32_t)(16384 + (buf) * 16384))
#define RED_OFF 0u
#define SMEMSZ  49152

// ---------------------------------------------------------------------------
// prep: fp16 of W_e, plane layout [s][chunk][a][8]
// ---------------------------------------------------------------------------
__global__ void prepW_kernel(const float* __restrict__ We) {
    int i = blockIdx.x * blockDim.x + threadIdx.x;
    if (i >= AA * EE) return;
    int a = i >> 10, e = i & 1023;
    int s = e >> 4, c = (e >> 3) & 1, kk = e & 7;
    g_W16[(((size_t)s * 2 + c) * AA + a) * 8 + kk] = __float2half(We[i]);
}

// ---------------------------------------------------------------------------
// dproj[n][a] = dec_h[n]·W_d[a]  (exact fp32). Block per n, thread per a.
// ---------------------------------------------------------------------------
__global__ __launch_bounds__(512) void dproj_kernel(const float* __restrict__ dec_h,
                                                    const float* __restrict__ W_d) {
    __shared__ float dsh[DD];
    const int n = blockIdx.x, a = threadIdx.x;
    for (int k = a; k < DD; k += 512) dsh[k] = dec_h[(size_t)n * DD + k];
    __syncthreads();
    const float4* wd = (const float4*)(W_d + (size_t)a * DD);
    float acc = 0.f;
    #pragma unroll 8
    for (int k4 = 0; k4 < DD / 4; k4++) {
        float4 w = wd[k4];
        acc += w.x * dsh[k4 * 4] + w.y * dsh[k4 * 4 + 1] +
               w.z * dsh[k4 * 4 + 2] + w.w * dsh[k4 * 4 + 3];
    }
    g_dproj[n * AA + a] = acc;
}

// ---------------------------------------------------------------------------
// scores: block = (t-pair, a-half). M=128 (2t x 64n), N=256 (a-half), K=32/iter.
// 512 threads, 16 warps, warp-tile 64x32. Conflict-free plane smem layout.
// ---------------------------------------------------------------------------
__global__ __launch_bounds__(512, 1) void scores_mma_kernel(
    const float* __restrict__ enc, const float* __restrict__ v) {
    extern __shared__ char smem[];
    const uint32_t sb = smem_u32(smem);
    const int tid = threadIdx.x;
    const int tile = blockIdx.x >> 1;       // t-pair (0..1023)
    const int half = blockIdx.x & 1;        // a-half
    const int lane = tid & 31;
    const int wid = tid >> 5;               // 0..15
    const int mh = wid >> 3;                // m-half
    const int ng = wid & 7;                 // n-group (32 cols)
    const int row = tid >> 2;               // A loader row 0..127
    const int k4 = (tid & 3) * 4;           // A loader k offset in panel
    const int aBase = half * 256;

    const size_t rowBase = ((size_t)tile * 128 + row) * EE;

    float c[4][4][4] = {};

    // W copy: thread -> (panel wp, row wr); copies both chunks
    const int wp = tid >> 8;
    const int wr = tid & 255;
    auto cpW = [&](int i, int b) {
        const int s = 2 * i + wp;
        uint32_t dst = sb + W_OFF(b) + (uint32_t)wp * 8192 + (uint32_t)wr * 16;
        cp16(dst,        g_W16 + (((size_t)s * 2 + 0) * AA + aBase + wr) * 8);
        cp16(dst + 4096, g_W16 + (((size_t)s * 2 + 1) * AA + aBase + wr) * 8);
    };

    // A store: packed fp16 convert, 8B per panel into plane layout
    const uint32_t aStoreOff = (uint32_t)((k4 >> 3) * 2048 + row * 16 + (k4 & 7) * 2);
    auto stsA = [&](int b, float4 x0, float4 x1) {
        __half2 h0a = __floats2half2_rn(x0.x, x0.y);
        __half2 h0b = __floats2half2_rn(x0.z, x0.w);
        __half2 h1a = __floats2half2_rn(x1.x, x1.y);
        __half2 h1b = __floats2half2_rn(x1.z, x1.w);
        uint2 p0, p1;
        p0.x = *(uint32_t*)&h0a; p0.y = *(uint32_t*)&h0b;
        p1.x = *(uint32_t*)&h1a; p1.y = *(uint32_t*)&h1b;
        *(uint2*)(smem + A_OFF(b) + aStoreOff) = p0;            // panel 0
        *(uint2*)(smem + A_OFF(b) + 4096 + aStoreOff) = p1;     // panel 1
    };

    // ldmatrix address components (plane layout, conflict-free: 16B row stride)
    const uint32_t aRowOff = (uint32_t)(lane >> 4) * 2048 +
                             (uint32_t)(mh * 64 + (lane & 15)) * 16;
    const uint32_t bRowOff = (uint32_t)((lane >> 3) & 1) * 4096 +
                             (uint32_t)(ng * 32 + (lane >> 4) * 8 + (lane & 7)) * 16;

    // ---- prologue ----
    cpW(0, 0); cp_commit();
    float4 x0 = *(const float4*)(enc + rowBase + k4);
    float4 x1 = *(const float4*)(enc + rowBase + 16 + k4);

    #pragma unroll 1
    for (int i = 0; i < NIT; i++) {
        const int b = i & 1;
        stsA(b, x0, x1);
        cp_wait0();        // this thread's W(i) copies done
        __syncthreads();   // everyone's W(i) + A stores visible
        if (i + 1 < NIT) {
            x0 = *(const float4*)(enc + rowBase + (size_t)(i + 1) * 32 + k4);
            x1 = *(const float4*)(enc + rowBase + (size_t)(i + 1) * 32 + 16 + k4);
            cpW(i + 1, b ^ 1);
            cp_commit();
        }

        #pragma unroll
        for (int p = 0; p < 2; p++) {
            uint32_t aH[4][4];
            #pragma unroll
            for (int mi = 0; mi < 4; mi++)
                ldmx4(aH[mi], sb + A_OFF(b) + (uint32_t)p * 4096 + (uint32_t)mi * 256 + aRowOff);
            uint32_t bb[2][4];   // [ntp]: m0,m1 = nt even, m2,m3 = nt odd
            #pragma unroll
            for (int ntp = 0; ntp < 2; ntp++)
                ldmx4(bb[ntp], sb + W_OFF(b) + (uint32_t)p * 8192 + (uint32_t)ntp * 256 + bRowOff);
            #pragma unroll
            for (int nt = 0; nt < 4; nt++) {
                const uint32_t b0 = bb[nt >> 1][(nt & 1) * 2];
                const uint32_t b1 = bb[nt >> 1][(nt & 1) * 2 + 1];
                #pragma unroll
                for (int mi = 0; mi < 4; mi++)
                    mma16816(c[mi][nt], aH[mi], b0, b1);
            }
        }
    }

    // ---- epilogue: + dproj (exact fp32), tanh, dot v, reduce ----
    const int g = lane >> 2, t4 = lane & 3;
    float p[8];
    #pragma unroll
    for (int i = 0; i < 8; i++) p[i] = 0.f;

    #pragma unroll
    for (int nt = 0; nt < 4; nt++) {
        const int a0 = aBase + ng * 32 + nt * 8 + t4 * 2;
        const float v0 = __ldg(v + a0), v1 = __ldg(v + a0 + 1);
        #pragma unroll
        for (int mi = 0; mi < 4; mi++) {
            const int n0 = mi * 16 + g;
            float2 d0 = *(const float2*)(g_dproj + (size_t)n0 * AA + a0);
            float2 d1 = *(const float2*)(g_dproj + (size_t)(n0 + 8) * AA + a0);
            p[mi * 2 + 0] += tanh_fast(c[mi][nt][0] + d0.x) * v0 +
                             tanh_fast(c[mi][nt][1] + d0.y) * v1;
            p[mi * 2 + 1] += tanh_fast(c[mi][nt][2] + d1.x) * v0 +
                             tanh_fast(c[mi][nt][3] + d1.y) * v1;
        }
    }
    #pragma unroll
    for (int i = 0; i < 8; i++) {
        p[i] += __shfl_down_sync(0xffffffffu, p[i], 1);
        p[i] += __shfl_down_sync(0xffffffffu, p[i], 2);
    }
    float* red = (float*)(smem + RED_OFF);   // [128][8], reuses A region
    __syncthreads();
    if (t4 == 0) {
        #pragma unroll
        for (int mi = 0; mi < 4; mi++) {
            int r0 = mh * 64 + mi * 16 + g;
            red[r0 * 8 + ng] = p[mi * 2 + 0];
            red[(r0 + 8) * 8 + ng] = p[mi * 2 + 1];
        }
    }
    __syncthreads();
    if (tid < 128) {
        float s = 0.f;
        #pragma unroll
        for (int w = 0; w < 8; w++) s += red[tid * 8 + w];
        int t = tile * 2 + (tid >> 6);
        int n = tid & 63;
        g_scoresP[(size_t)half * (NN * TT) + (size_t)n * TT + t] = s;
    }
}

// ---------------------------------------------------------------------------
// softmax over T per column n (sums the two a-half partials)
// ---------------------------------------------------------------------------
__global__ void softmax_kernel(float* __restrict__ out_alpha) {
    const int n = blockIdx.x, tid = threadIdx.x;
    __shared__ float sm[256];
    const float* s0 = g_scoresP + (size_t)n * TT;
    const float* s1 = g_scoresP + (size_t)NN * TT + (size_t)n * TT;

    float m = -1e30f;
    for (int t = tid; t < TT; t += 256) m = fmaxf(m, s0[t] + s1[t]);
    sm[tid] = m; __syncthreads();
    #pragma unroll
    for (int o = 128; o; o >>= 1) {
        if (tid < o) sm[tid] = fmaxf(sm[tid], sm[tid + o]);
        __syncthreads();
    }
    m = sm[0];
    __syncthreads();

    float acc = 0.f;
    for (int t = tid; t < TT; t += 256) acc += expf(s0[t] + s1[t] - m);
    sm[tid] = acc; __syncthreads();
    #pragma unroll
    for (int o = 128; o; o >>= 1) {
        if (tid < o) sm[tid] += sm[tid + o];
        __syncthreads();
    }
    const float inv = 1.0f / sm[0];

    for (int t = tid; t < TT; t += 256) {
        float al = expf(s0[t] + s1[t] - m) * inv;
        g_alphaT[(size_t)n * TT + t] = al;
        out_alpha[(size_t)t * NN + n] = al;
    }
}

// ---------------------------------------------------------------------------
// ctx = alpha^T * enc  (partials + reduce) — at DRAM roofline already
// ---------------------------------------------------------------------------
__global__ __launch_bounds__(256) void ctx_partial_kernel(const float* __restrict__ enc) {
    const int tc = blockIdx.x & (TCH - 1);
    const int n = blockIdx.x / TCH;
    const int e0 = threadIdx.x * 4;
    float4 acc = make_float4(0.f, 0.f, 0.f, 0.f);
    const int tBeg = tc * (TT / TCH);
    #pragma unroll 4
    for (int t = tBeg; t < tBeg + TT / TCH; ++t) {
        float al = g_alphaT[(size_t)n * TT + t];
        float4 ev = *(const float4*)(enc + ((size_t)t * NN + n) * EE + e0);
        acc.x += al * ev.x; acc.y += al * ev.y;
        acc.z += al * ev.z; acc.w += al * ev.w;
    }
    *(float4*)&g_part[((size_t)tc * NN + n) * EE + e0] = acc;
}

__global__ void ctx_reduce_kernel(float* __restrict__ out_ctx) {
    const int n = blockIdx.x;
    const int e0 = threadIdx.x * 4;
    float4 acc = make_float4(0.f, 0.f, 0.f, 0.f);
    #pragma unroll
    for (int tc = 0; tc < TCH; ++tc) {
        float4 p = *(const float4*)&g_part[((size_t)tc * NN + n) * EE + e0];
        acc.x += p.x; acc.y += p.y; acc.z += p.z; acc.w += p.w;
    }
    *(float4*)&out_ctx[(size_t)n * EE + e0] = acc;
}

// ---------------------------------------------------------------------------
extern "C" void kernel_launch(void* const* d_in, const int* in_sizes, int n_in,
                              void* d_out, int out_size) {
    const float* enc = (const float*)d_in[0];   // [T, N, E]
    const float* dec = (const float*)d_in[1];   // [N, D]
    const float* We  = (const float*)d_in[2];   // [A, E]
    const float* Wd  = (const float*)d_in[3];   // [A, D]
    const float* v   = (const float*)d_in[4];   // [1, A]

    float* out = (float*)d_out;
    float* out_ctx = out;                 // [N, E]
    float* out_alpha = out + NN * EE;     // [T, N]

    prepW_kernel<<<(AA * EE + 255) / 256, 256>>>(We);
    dproj_kernel<<<NN, 512>>>(dec, Wd);
    scores_mma_kernel<<<TT, 512, SMEMSZ>>>(enc, v);
    softmax_kernel<<<NN, 256>>>(out_alpha);
    ctx_partial_kernel<<<NN * TCH, 256>>>(enc);
    ctx_reduce_kernel<<<NN, 256>>>(out_ctx);
}